// round 3
// baseline (speedup 1.0000x reference)
#include <cuda_runtime.h>

#define NV 50000
#define NE 10000
#define NP 800000
#define D  256
#define CAPE 192
#define CAPV 64

// ---------------- device scratch (no runtime allocation allowed) -----------
__device__ float g_H[NV * D];        // 51.2 MB  projected vertex features
__device__ float g_ef[NE * D];       // 10.2 MB  hyperedge features
__device__ int   g_ecnt[NE];
__device__ int   g_vcnt[NV];
__device__ int   g_eslot[NE * CAPE]; // 7.7 MB   members (vertices) per edge
__device__ int   g_vslot[NV * CAPV]; // 12.8 MB  incident edges per vertex

// ---------------- zero the counters ----------------------------------------
__global__ void k_zero() {
    int i = blockIdx.x * blockDim.x + threadIdx.x;
    if (i < NE) g_ecnt[i] = 0;
    if (i < NV) g_vcnt[i] = 0;
}

// ---------------- build inverted slot lists (one pass, int atomics only) ---
__global__ void k_build(const int* __restrict__ v_idx,
                        const int* __restrict__ e_idx) {
    int i = blockIdx.x * blockDim.x + threadIdx.x;
    if (i >= NP) return;
    int v = v_idx[i];
    int e = e_idx[i];
    int pe = atomicAdd(&g_ecnt[e], 1);
    if (pe < CAPE) g_eslot[e * CAPE + pe] = v;
    int pv = atomicAdd(&g_vcnt[v], 1);
    if (pv < CAPV) g_vslot[v * CAPV + pv] = e;
}

// ---------------- SGEMM: H = X*W + b  (fp32, 64x64 tile, 4x4 per thread) ---
__global__ __launch_bounds__(256) void k_gemm(const float* __restrict__ X,
                                              const float* __restrict__ W,
                                              const float* __restrict__ bias) {
    __shared__ float As[64][20];   // 64 rows x 16 k, padded (float4-aligned rows)
    __shared__ float Bs[16][64];

    const int tid = threadIdx.x;          // 256 threads
    const int tx  = tid & 15;             // 0..15 -> 4 cols each
    const int ty  = tid >> 4;             // 0..15 -> 4 rows each
    const int brow = blockIdx.x * 64;
    const int bcol = blockIdx.y * 64;

    const int arow  = tid >> 2;           // 0..63
    const int acol4 = (tid & 3) * 4;      // 0,4,8,12
    const int brl   = tid >> 4;           // 0..15
    const int bcl4  = (tid & 15) * 4;     // 0..60

    float acc[4][4] = {};

    for (int k0 = 0; k0 < D; k0 += 16) {
        float4 a4 = make_float4(0.f, 0.f, 0.f, 0.f);
        int gr = brow + arow;
        if (gr < NV)
            a4 = *(const float4*)(X + gr * D + k0 + acol4);
        *(float4*)&As[arow][acol4] = a4;

        float4 b4 = *(const float4*)(W + (k0 + brl) * D + bcol + bcl4);
        *(float4*)&Bs[brl][bcl4] = b4;
        __syncthreads();

#pragma unroll
        for (int k = 0; k < 16; k++) {
            float a[4], b[4];
#pragma unroll
            for (int i = 0; i < 4; i++) a[i] = As[ty * 4 + i][k];
#pragma unroll
            for (int j = 0; j < 4; j++) b[j] = Bs[k][tx * 4 + j];
#pragma unroll
            for (int i = 0; i < 4; i++)
#pragma unroll
                for (int j = 0; j < 4; j++)
                    acc[i][j] = fmaf(a[i], b[j], acc[i][j]);
        }
        __syncthreads();
    }

    float4 bv = *(const float4*)(bias + bcol + tx * 4);
#pragma unroll
    for (int i = 0; i < 4; i++) {
        int r = brow + ty * 4 + i;
        if (r < NV) {
            float4 o;
            o.x = acc[i][0] + bv.x;
            o.y = acc[i][1] + bv.y;
            o.z = acc[i][2] + bv.z;
            o.w = acc[i][3] + bv.w;
            *(float4*)(g_H + r * D + bcol + tx * 4) = o;
        }
    }
}

// ---------------- v2e mean: pull member H rows, no atomics -----------------
// 4 segments per 256-thread block; 64 lanes per segment, float4 over 256 dims
__global__ __launch_bounds__(256) void k_v2e() {
    const int g    = threadIdx.x >> 6;
    const int lane = threadIdx.x & 63;
    const int e    = blockIdx.x * 4 + g;
    if (e >= NE) return;

    const int n = g_ecnt[e];
    const int m = min(n, CAPE);
    const int* __restrict__ sl = g_eslot + e * CAPE;
    const int off = lane * 4;

    float4 acc = make_float4(0.f, 0.f, 0.f, 0.f);
    int i = 0;
    for (; i + 4 <= m; i += 4) {
        int v0 = sl[i], v1 = sl[i + 1], v2 = sl[i + 2], v3 = sl[i + 3];
        float4 f0 = *(const float4*)(g_H + v0 * D + off);
        float4 f1 = *(const float4*)(g_H + v1 * D + off);
        float4 f2 = *(const float4*)(g_H + v2 * D + off);
        float4 f3 = *(const float4*)(g_H + v3 * D + off);
        acc.x += (f0.x + f1.x) + (f2.x + f3.x);
        acc.y += (f0.y + f1.y) + (f2.y + f3.y);
        acc.z += (f0.z + f1.z) + (f2.z + f3.z);
        acc.w += (f0.w + f1.w) + (f2.w + f3.w);
    }
    for (; i < m; i++) {
        int v = sl[i];
        float4 f = *(const float4*)(g_H + v * D + off);
        acc.x += f.x; acc.y += f.y; acc.z += f.z; acc.w += f.w;
    }
    float inv = 1.f / (float)max(n, 1);
    float4 o = make_float4(acc.x * inv, acc.y * inv, acc.z * inv, acc.w * inv);
    *(float4*)(g_ef + e * D + off) = o;
}

// ---------------- e2v mean + leaky relu, writes d_out ----------------------
__global__ __launch_bounds__(256) void k_e2v(float* __restrict__ out) {
    const int g    = threadIdx.x >> 6;
    const int lane = threadIdx.x & 63;
    const int v    = blockIdx.x * 4 + g;
    if (v >= NV) return;

    const int n = g_vcnt[v];
    const int m = min(n, CAPV);
    const int* __restrict__ sl = g_vslot + v * CAPV;
    const int off = lane * 4;

    float4 acc = make_float4(0.f, 0.f, 0.f, 0.f);
    int i = 0;
    for (; i + 4 <= m; i += 4) {
        int e0 = sl[i], e1 = sl[i + 1], e2 = sl[i + 2], e3 = sl[i + 3];
        float4 f0 = *(const float4*)(g_ef + e0 * D + off);
        float4 f1 = *(const float4*)(g_ef + e1 * D + off);
        float4 f2 = *(const float4*)(g_ef + e2 * D + off);
        float4 f3 = *(const float4*)(g_ef + e3 * D + off);
        acc.x += (f0.x + f1.x) + (f2.x + f3.x);
        acc.y += (f0.y + f1.y) + (f2.y + f3.y);
        acc.z += (f0.z + f1.z) + (f2.z + f3.z);
        acc.w += (f0.w + f1.w) + (f2.w + f3.w);
    }
    for (; i < m; i++) {
        int e = sl[i];
        float4 f = *(const float4*)(g_ef + e * D + off);
        acc.x += f.x; acc.y += f.y; acc.z += f.z; acc.w += f.w;
    }
    float inv = 1.f / (float)max(n, 1);
    float4 o;
    float x;
    x = acc.x * inv; o.x = (x >= 0.f) ? x : 0.01f * x;
    x = acc.y * inv; o.y = (x >= 0.f) ? x : 0.01f * x;
    x = acc.z * inv; o.z = (x >= 0.f) ? x : 0.01f * x;
    x = acc.w * inv; o.w = (x >= 0.f) ? x : 0.01f * x;
    *(float4*)(out + v * D + off) = o;
}

// ---------------- launch ----------------------------------------------------
extern "C" void kernel_launch(void* const* d_in, const int* in_sizes, int n_in,
                              void* d_out, int out_size) {
    const float* X    = (const float*)d_in[0];
    const float* W    = (const float*)d_in[1];
    const float* bias = (const float*)d_in[2];
    const int*   v_idx = (const int*)d_in[3];
    const int*   e_idx = (const int*)d_in[4];
    float* out = (float*)d_out;

    k_zero<<<(NV + 255) / 256, 256>>>();

    dim3 gg((NV + 63) / 64, D / 64);
    k_gemm<<<gg, 256>>>(X, W, bias);

    k_build<<<(NP + 255) / 256, 256>>>(v_idx, e_idx);

    k_v2e<<<(NE + 3) / 4, 256>>>();
    k_e2v<<<(NV + 3) / 4, 256>>>(out);
}

// round 5
// speedup vs baseline: 1.2570x; 1.2570x over previous
#include <cuda_runtime.h>
#include <cuda_bf16.h>
#include <cstdint>

#define NV 50000
#define NE 10000
#define NP 800000
#define D  256
#define CAPE 192
#define CAPV 64

// ---------------- device scratch (no runtime allocation allowed) -----------
__device__ float g_H[NV * D];                 // 51.2 MB projected vertex features
__device__ float g_ef[NE * D];                // 10.2 MB hyperedge features
__device__ int   g_ecnt[NE];
__device__ int   g_vcnt[NV];
__device__ int   g_eslot[NE * CAPE];
__device__ int   g_vslot[NV * CAPV];
__device__ __nv_bfloat16 g_Xh[NV * D];        // 25.6 MB  bf16 hi of X
__device__ __nv_bfloat16 g_Xl[NV * D];        // 25.6 MB  bf16 lo of X
__device__ __nv_bfloat16 g_Wth[D * D];        // W^T hi   [n][k]
__device__ __nv_bfloat16 g_Wtl[D * D];        // W^T lo   [n][k]

__device__ __forceinline__ uint32_t smem_u32(const void* p) {
    uint32_t a;
    asm("{ .reg .u64 t; cvta.to.shared.u64 t, %1; cvt.u32.u64 %0, t; }"
        : "=r"(a) : "l"(p));
    return a;
}

// ---------------- zero the counters ----------------------------------------
__global__ void k_zero() {
    int i = blockIdx.x * blockDim.x + threadIdx.x;
    if (i < NE) g_ecnt[i] = 0;
    if (i < NV) g_vcnt[i] = 0;
}

// ---------------- build inverted slot lists ---------------------------------
__global__ void k_build(const int* __restrict__ v_idx,
                        const int* __restrict__ e_idx) {
    int i = blockIdx.x * blockDim.x + threadIdx.x;
    if (i >= NP) return;
    int v = v_idx[i];
    int e = e_idx[i];
    int pe = atomicAdd(&g_ecnt[e], 1);
    if (pe < CAPE) g_eslot[e * CAPE + pe] = v;
    int pv = atomicAdd(&g_vcnt[v], 1);
    if (pv < CAPV) g_vslot[v * CAPV + pv] = e;
}

// ---------------- split X into bf16 hi/lo -----------------------------------
__global__ void k_split_x(const float* __restrict__ X) {
    int i = blockIdx.x * blockDim.x + threadIdx.x;   // one per 4 elems
    if (i >= NV * D / 4) return;
    float4 x = ((const float4*)X)[i];
    __nv_bfloat16 h0 = __float2bfloat16(x.x);
    __nv_bfloat16 h1 = __float2bfloat16(x.y);
    __nv_bfloat16 h2 = __float2bfloat16(x.z);
    __nv_bfloat16 h3 = __float2bfloat16(x.w);
    __nv_bfloat16 l0 = __float2bfloat16(x.x - __bfloat162float(h0));
    __nv_bfloat16 l1 = __float2bfloat16(x.y - __bfloat162float(h1));
    __nv_bfloat16 l2 = __float2bfloat16(x.z - __bfloat162float(h2));
    __nv_bfloat16 l3 = __float2bfloat16(x.w - __bfloat162float(h3));
    uint2 hv, lv;
    hv.x = ((uint32_t)__bfloat16_as_ushort(h1) << 16) | __bfloat16_as_ushort(h0);
    hv.y = ((uint32_t)__bfloat16_as_ushort(h3) << 16) | __bfloat16_as_ushort(h2);
    lv.x = ((uint32_t)__bfloat16_as_ushort(l1) << 16) | __bfloat16_as_ushort(l0);
    lv.y = ((uint32_t)__bfloat16_as_ushort(l3) << 16) | __bfloat16_as_ushort(l2);
    ((uint2*)g_Xh)[i] = hv;
    ((uint2*)g_Xl)[i] = lv;
}

// ---------------- split + transpose W ---------------------------------------
__global__ void k_split_w(const float* __restrict__ W) {
    int i = blockIdx.x * blockDim.x + threadIdx.x;
    if (i >= D * D) return;
    int k = i >> 8, n = i & 255;
    float w = W[k * D + n];
    __nv_bfloat16 h = __float2bfloat16(w);
    __nv_bfloat16 l = __float2bfloat16(w - __bfloat162float(h));
    g_Wth[n * D + k] = h;
    g_Wtl[n * D + k] = l;
}

// ---------------- bf16-split GEMM via mma.sync (HMMA): H = X*W + b ----------
// CTA tile 128x128, 8 warps (4 along M x 2 along N), warp tile 32x64.
// K = 3 terms x 256 = 12 chunks of 64. Register-prefetched single-buffer SMEM.
#define MT 128
#define NT 128
#define KC 64
#define NCHUNK 12

__global__ __launch_bounds__(256) void k_gemm_mma(const float* __restrict__ bias) {
    __shared__ __align__(1024) char sA[MT * KC * 2];   // 16 KB, SW128 swizzled
    __shared__ __align__(1024) char sB[NT * KC * 2];   // 16 KB, SW128 swizzled

    const int tid  = threadIdx.x;
    const int wid  = tid >> 5;
    const int lane = tid & 31;
    const int mbase = blockIdx.x * MT;
    const int nbase = blockIdx.y * NT;
    const int wm = wid & 3;        // warp row  (0..3) -> m 32
    const int wn = wid >> 2;       // warp col  (0..1) -> n 64

    const uint32_t sA_u = smem_u32(sA);
    const uint32_t sB_u = smem_u32(sB);

    // ldmatrix per-lane addressing: row = base + (lane&15), k-half = (lane>>4)*16B
    const uint32_t xorv = (uint32_t)(lane & 7) << 4;   // SW128 xor, constant per lane
    uint32_t aoff[2], boff[4];
#pragma unroll
    for (int t = 0; t < 2; t++)
        aoff[t] = (uint32_t)((wm * 32 + t * 16 + (lane & 15)) * 128 + (lane >> 4) * 16);
#pragma unroll
    for (int jj = 0; jj < 4; jj++)
        boff[jj] = (uint32_t)((wn * 64 + jj * 16 + (lane & 15)) * 128 + (lane >> 4) * 16);

    // gmem load pattern: thread handles rows rt+32q (q=0..3), fixed 16B segment
    const int rt  = tid >> 3;
    const int seg = tid & 7;

    float acc[2][8][4];
#pragma unroll
    for (int t = 0; t < 2; t++)
#pragma unroll
        for (int j = 0; j < 8; j++)
#pragma unroll
            for (int q = 0; q < 4; q++) acc[t][j][q] = 0.f;

    uint4 pf[8];

#define LOADC(c) do {                                                          \
    int term = (c) >> 2;                                                       \
    int kc   = ((c) & 3) * KC;                                                 \
    const __nv_bfloat16* __restrict__ Ab = (term < 2)  ? g_Xh  : g_Xl;         \
    const __nv_bfloat16* __restrict__ Bb = (term == 1) ? g_Wtl : g_Wth;        \
    _Pragma("unroll")                                                          \
    for (int q = 0; q < 4; q++) {                                              \
        int r = q * 32 + rt;                                                   \
        int gr = mbase + r;                                                    \
        pf[q] = (gr < NV)                                                      \
            ? *(const uint4*)(Ab + (size_t)gr * D + kc + seg * 8)              \
            : make_uint4(0u, 0u, 0u, 0u);                                      \
        pf[4 + q] = *(const uint4*)(Bb + (size_t)(nbase + r) * D + kc + seg * 8); \
    } } while (0)

#define STOREC() do {                                                          \
    _Pragma("unroll")                                                          \
    for (int q = 0; q < 4; q++) {                                              \
        int r = q * 32 + rt;                                                   \
        uint32_t off = (uint32_t)(r * 128 + seg * 16);                         \
        uint32_t sw  = off ^ (uint32_t)((r & 7) << 4);                         \
        *(uint4*)(sA + sw) = pf[q];                                            \
        *(uint4*)(sB + sw) = pf[4 + q];                                        \
    } } while (0)

    LOADC(0);
    STOREC();
    __syncthreads();

    for (int c = 0; c < NCHUNK; c++) {
        if (c + 1 < NCHUNK) LOADC(c + 1);   // prefetch next chunk into registers
#pragma unroll
        for (int s = 0; s < 4; s++) {       // 4 x k16 steps per 64-wide chunk
            const uint32_t kb = (uint32_t)(s * 32);
            uint32_t ar[2][4], br[4][4];
#pragma unroll
            for (int t = 0; t < 2; t++) {
                uint32_t addr = sA_u + ((aoff[t] + kb) ^ xorv);
                asm volatile(
                    "ldmatrix.sync.aligned.m8n8.x4.shared.b16 {%0,%1,%2,%3}, [%4];"
                    : "=r"(ar[t][0]), "=r"(ar[t][1]), "=r"(ar[t][2]), "=r"(ar[t][3])
                    : "r"(addr));
            }
#pragma unroll
            for (int jj = 0; jj < 4; jj++) {
                uint32_t addr = sB_u + ((boff[jj] + kb) ^ xorv);
                asm volatile(
                    "ldmatrix.sync.aligned.m8n8.x4.shared.b16 {%0,%1,%2,%3}, [%4];"
                    : "=r"(br[jj][0]), "=r"(br[jj][1]), "=r"(br[jj][2]), "=r"(br[jj][3])
                    : "r"(addr));
            }
#pragma unroll
            for (int t = 0; t < 2; t++)
#pragma unroll
                for (int j = 0; j < 8; j++) {
                    const int jj = j >> 1, h = j & 1;
                    asm volatile(
                        "mma.sync.aligned.m16n8k16.row.col.f32.bf16.bf16.f32 "
                        "{%0,%1,%2,%3}, {%4,%5,%6,%7}, {%8,%9}, {%0,%1,%2,%3};"
                        : "+f"(acc[t][j][0]), "+f"(acc[t][j][1]),
                          "+f"(acc[t][j][2]), "+f"(acc[t][j][3])
                        : "r"(ar[t][0]), "r"(ar[t][1]), "r"(ar[t][2]), "r"(ar[t][3]),
                          "r"(br[jj][h]), "r"(br[jj][2 + h]));
                }
        }
        __syncthreads();
        if (c + 1 < NCHUNK) {
            STOREC();
            __syncthreads();
        }
    }

    // epilogue: C-frag layout -> g_H with bias
    const int r0 = lane >> 2;
    const int c2 = (lane & 3) * 2;
#pragma unroll
    for (int t = 0; t < 2; t++) {
        int row = mbase + wm * 32 + t * 16 + r0;
#pragma unroll
        for (int j = 0; j < 8; j++) {
            int col = nbase + wn * 64 + j * 8 + c2;
            float2 bv = *(const float2*)(bias + col);
            if (row < NV) {
                float2 o;
                o.x = acc[t][j][0] + bv.x;
                o.y = acc[t][j][1] + bv.y;
                *(float2*)(g_H + (size_t)row * D + col) = o;
            }
            if (row + 8 < NV) {
                float2 o;
                o.x = acc[t][j][2] + bv.x;
                o.y = acc[t][j][3] + bv.y;
                *(float2*)(g_H + (size_t)(row + 8) * D + col) = o;
            }
        }
    }
#undef LOADC
#undef STOREC
}

// ---------------- v2e mean: pull member H rows, 8-wide MLP -------------------
__global__ __launch_bounds__(256) void k_v2e() {
    const int g    = threadIdx.x >> 6;
    const int lane = threadIdx.x & 63;
    const int e    = blockIdx.x * 4 + g;
    if (e >= NE) return;

    const int n = g_ecnt[e];
    const int m = min(n, CAPE);
    const int* __restrict__ sl = g_eslot + e * CAPE;
    const int off = lane * 4;

    float4 acc = make_float4(0.f, 0.f, 0.f, 0.f);
    int i = 0;
    for (; i + 8 <= m; i += 8) {
        int v0 = sl[i], v1 = sl[i+1], v2 = sl[i+2], v3 = sl[i+3];
        int v4 = sl[i+4], v5 = sl[i+5], v6 = sl[i+6], v7 = sl[i+7];
        float4 f0 = *(const float4*)(g_H + (size_t)v0 * D + off);
        float4 f1 = *(const float4*)(g_H + (size_t)v1 * D + off);
        float4 f2 = *(const float4*)(g_H + (size_t)v2 * D + off);
        float4 f3 = *(const float4*)(g_H + (size_t)v3 * D + off);
        float4 f4 = *(const float4*)(g_H + (size_t)v4 * D + off);
        float4 f5 = *(const float4*)(g_H + (size_t)v5 * D + off);
        float4 f6 = *(const float4*)(g_H + (size_t)v6 * D + off);
        float4 f7 = *(const float4*)(g_H + (size_t)v7 * D + off);
        acc.x += ((f0.x + f1.x) + (f2.x + f3.x)) + ((f4.x + f5.x) + (f6.x + f7.x));
        acc.y += ((f0.y + f1.y) + (f2.y + f3.y)) + ((f4.y + f5.y) + (f6.y + f7.y));
        acc.z += ((f0.z + f1.z) + (f2.z + f3.z)) + ((f4.z + f5.z) + (f6.z + f7.z));
        acc.w += ((f0.w + f1.w) + (f2.w + f3.w)) + ((f4.w + f5.w) + (f6.w + f7.w));
    }
    for (; i < m; i++) {
        int v = sl[i];
        float4 f = *(const float4*)(g_H + (size_t)v * D + off);
        acc.x += f.x; acc.y += f.y; acc.z += f.z; acc.w += f.w;
    }
    float inv = 1.f / (float)max(n, 1);
    float4 o = make_float4(acc.x * inv, acc.y * inv, acc.z * inv, acc.w * inv);
    *(float4*)(g_ef + (size_t)e * D + off) = o;
}

// ---------------- e2v mean + leaky relu, writes d_out ------------------------
__global__ __launch_bounds__(256) void k_e2v(float* __restrict__ out) {
    const int g    = threadIdx.x >> 6;
    const int lane = threadIdx.x & 63;
    const int v    = blockIdx.x * 4 + g;
    if (v >= NV) return;

    const int n = g_vcnt[v];
    const int m = min(n, CAPV);
    const int* __restrict__ sl = g_vslot + v * CAPV;
    const int off = lane * 4;

    float4 acc = make_float4(0.f, 0.f, 0.f, 0.f);
    int i = 0;
    for (; i + 4 <= m; i += 4) {
        int e0 = sl[i], e1 = sl[i + 1], e2 = sl[i + 2], e3 = sl[i + 3];
        float4 f0 = *(const float4*)(g_ef + (size_t)e0 * D + off);
        float4 f1 = *(const float4*)(g_ef + (size_t)e1 * D + off);
        float4 f2 = *(const float4*)(g_ef + (size_t)e2 * D + off);
        float4 f3 = *(const float4*)(g_ef + (size_t)e3 * D + off);
        acc.x += (f0.x + f1.x) + (f2.x + f3.x);
        acc.y += (f0.y + f1.y) + (f2.y + f3.y);
        acc.z += (f0.z + f1.z) + (f2.z + f3.z);
        acc.w += (f0.w + f1.w) + (f2.w + f3.w);
    }
    for (; i < m; i++) {
        int e = sl[i];
        float4 f = *(const float4*)(g_ef + (size_t)e * D + off);
        acc.x += f.x; acc.y += f.y; acc.z += f.z; acc.w += f.w;
    }
    float inv = 1.f / (float)max(n, 1);
    float4 o;
    float x;
    x = acc.x * inv; o.x = (x >= 0.f) ? x : 0.01f * x;
    x = acc.y * inv; o.y = (x >= 0.f) ? x : 0.01f * x;
    x = acc.z * inv; o.z = (x >= 0.f) ? x : 0.01f * x;
    x = acc.w * inv; o.w = (x >= 0.f) ? x : 0.01f * x;
    *(float4*)(out + (size_t)v * D + off) = o;
}

// ---------------- launch -----------------------------------------------------
extern "C" void kernel_launch(void* const* d_in, const int* in_sizes, int n_in,
                              void* d_out, int out_size) {
    const float* X     = (const float*)d_in[0];
    const float* W     = (const float*)d_in[1];
    const float* bias  = (const float*)d_in[2];
    const int*   v_idx = (const int*)d_in[3];
    const int*   e_idx = (const int*)d_in[4];
    float* out = (float*)d_out;

    k_zero<<<(NV + 255) / 256, 256>>>();
    k_build<<<(NP + 255) / 256, 256>>>(v_idx, e_idx);
    k_split_x<<<(NV * D / 4 + 255) / 256, 256>>>(X);
    k_split_w<<<(D * D + 255) / 256, 256>>>(W);

    dim3 gg((NV + MT - 1) / MT, D / NT);   // (391, 2)
    k_gemm_mma<<<gg, 256>>>(bias);

    k_v2e<<<(NE + 3) / 4, 256>>>();
    k_e2v<<<(NV + 3) / 4, 256>>>(out);
}

// round 7
// speedup vs baseline: 1.3779x; 1.0962x over previous
#include <cuda_runtime.h>
#include <cuda_bf16.h>
#include <cstdint>

#define NV 50000
#define NE 10000
#define NP 800000
#define D  256
#define CAPE 192
#define CAPV 64

// ---------------- device scratch (no runtime allocation allowed) -----------
__device__ float g_H[NV * D];                 // 51.2 MB projected vertex features
__device__ float g_ef[NE * D];                // 10.2 MB hyperedge features
__device__ int   g_ecnt[NE];
__device__ int   g_vcnt[NV];
__device__ int   g_eslot[NE * CAPE];
__device__ int   g_vslot[NV * CAPV];
__device__ __nv_bfloat16 g_Wth[D * D];        // W^T hi  [n][k]
__device__ __nv_bfloat16 g_Wtl[D * D];        // W^T lo  [n][k]

__device__ __forceinline__ uint32_t smem_u32(const void* p) {
    uint32_t a;
    asm("{ .reg .u64 t; cvta.to.shared.u64 t, %1; cvt.u32.u64 %0, t; }"
        : "=r"(a) : "l"(p));
    return a;
}

// ---------------- init: zero counters + split/transpose W -------------------
__global__ void k_init(const float* __restrict__ W) {
    int i = blockIdx.x * blockDim.x + threadIdx.x;   // 65536 threads
    if (i < NE) g_ecnt[i] = 0;
    if (i < NV) g_vcnt[i] = 0;
    // W split: i covers D*D exactly
    int k = i >> 8, n = i & 255;
    float w = W[k * D + n];
    __nv_bfloat16 h = __float2bfloat16(w);
    __nv_bfloat16 l = __float2bfloat16(w - __bfloat162float(h));
    g_Wth[n * D + k] = h;
    g_Wtl[n * D + k] = l;
}

// ---------------- build inverted slot lists ---------------------------------
__global__ void k_build(const int* __restrict__ v_idx,
                        const int* __restrict__ e_idx) {
    int i = blockIdx.x * blockDim.x + threadIdx.x;
    if (i >= NP) return;
    int v = v_idx[i];
    int e = e_idx[i];
    int pe = atomicAdd(&g_ecnt[e], 1);
    if (pe < CAPE) g_eslot[e * CAPE + pe] = v;
    int pv = atomicAdd(&g_vcnt[v], 1);
    if (pv < CAPV) g_vslot[v * CAPV + pv] = e;
}

// ---------------- fused split + bf16-split GEMM (HMMA): H = X*W + b ---------
// CTA tile 128x256, 8 warps (4 M x 2 N), warp tile 32x128.
// 4 physical K chunks of 64; per chunk, X fp32 loaded once, converted to
// hi/lo bf16 in SMEM; per k-step all 3 terms (XhWh + XhWl + XlWh) fused.
#define MT 128
#define KC 64
#define SM_XH 0
#define SM_XL (16 * 1024)
#define SM_WH (32 * 1024)
#define SM_WL (64 * 1024)
#define SMEM_BYTES (96 * 1024)

extern __shared__ __align__(1024) char dynsm[];

__global__ __launch_bounds__(256, 1) void k_gemm(const float* __restrict__ X,
                                                 const float* __restrict__ bias) {
    char* sm = dynsm;
    const int tid  = threadIdx.x;
    const int wid  = tid >> 5;
    const int lane = tid & 31;
    const int mbase = blockIdx.x * MT;
    const int wm = wid & 3;        // warp row (0..3) -> 32 rows
    const int wn = wid >> 2;       // warp col (0..1) -> 128 cols

    const uint32_t sm_u = smem_u32(sm);
    const uint32_t xorv = (uint32_t)(lane & 7) << 4;

    uint32_t aoff[2], boff[8];
#pragma unroll
    for (int t = 0; t < 2; t++)
        aoff[t] = (uint32_t)((wm * 32 + t * 16 + (lane & 15)) * 128 + (lane >> 4) * 16);
#pragma unroll
    for (int jj = 0; jj < 8; jj++)
        boff[jj] = (uint32_t)((wn * 128 + jj * 16 + (lane & 15)) * 128 + (lane >> 4) * 16);

    const int rt  = tid >> 3;      // 0..31
    const int seg = tid & 7;       // 16B segment

    float acc[2][16][4];
#pragma unroll
    for (int t = 0; t < 2; t++)
#pragma unroll
        for (int j = 0; j < 16; j++)
#pragma unroll
            for (int q = 0; q < 4; q++) acc[t][j][q] = 0.f;

    // X prefetch regs: 4 (row,seg) assignments x 2 float4
    float4 pf[8];

#define LOADX(c) do {                                                          \
    int kc = (c) * KC;                                                         \
    _Pragma("unroll")                                                          \
    for (int q = 0; q < 4; q++) {                                              \
        int gr = mbase + 32 * q + rt;                                          \
        if (gr < NV) {                                                         \
            const float* p = X + (size_t)gr * D + kc + seg * 8;                \
            pf[2 * q]     = *(const float4*)(p);                               \
            pf[2 * q + 1] = *(const float4*)(p + 4);                           \
        } else {                                                               \
            pf[2 * q] = pf[2 * q + 1] = make_float4(0.f, 0.f, 0.f, 0.f);       \
        }                                                                      \
    } } while (0)

    LOADX(0);

    for (int c = 0; c < 4; c++) {
        if (c > 0) __syncthreads();
        // --- convert X regs -> hi/lo bf16 smem tiles ---
#pragma unroll
        for (int q = 0; q < 4; q++) {
            int r = 32 * q + rt;
            uint32_t off = (uint32_t)(r * 128 + seg * 16);
            uint32_t sw  = off ^ (uint32_t)((r & 7) << 4);
            float f[8];
            f[0]=pf[2*q].x; f[1]=pf[2*q].y; f[2]=pf[2*q].z; f[3]=pf[2*q].w;
            f[4]=pf[2*q+1].x; f[5]=pf[2*q+1].y; f[6]=pf[2*q+1].z; f[7]=pf[2*q+1].w;
            uint32_t hw[4], lw[4];
#pragma unroll
            for (int p2 = 0; p2 < 4; p2++) {
                __nv_bfloat16 h0 = __float2bfloat16(f[2*p2]);
                __nv_bfloat16 h1 = __float2bfloat16(f[2*p2+1]);
                __nv_bfloat16 l0 = __float2bfloat16(f[2*p2]   - __bfloat162float(h0));
                __nv_bfloat16 l1 = __float2bfloat16(f[2*p2+1] - __bfloat162float(h1));
                hw[p2] = ((uint32_t)__bfloat16_as_ushort(h1) << 16) | __bfloat16_as_ushort(h0);
                lw[p2] = ((uint32_t)__bfloat16_as_ushort(l1) << 16) | __bfloat16_as_ushort(l0);
            }
            *(uint4*)(sm + SM_XH + sw) = make_uint4(hw[0], hw[1], hw[2], hw[3]);
            *(uint4*)(sm + SM_XL + sw) = make_uint4(lw[0], lw[1], lw[2], lw[3]);
        }
        // --- load W hi/lo chunk gmem -> smem ---
        {
            int kc = c * KC;
#pragma unroll
            for (int q = 0; q < 8; q++) {
                int n = 32 * q + rt;
                uint32_t off = (uint32_t)(n * 128 + seg * 16);
                uint32_t sw  = off ^ (uint32_t)((n & 7) << 4);
                uint4 hv = *(const uint4*)(g_Wth + (size_t)n * D + kc + seg * 8);
                uint4 lv = *(const uint4*)(g_Wtl + (size_t)n * D + kc + seg * 8);
                *(uint4*)(sm + SM_WH + sw) = hv;
                *(uint4*)(sm + SM_WL + sw) = lv;
            }
        }
        __syncthreads();
        if (c < 3) LOADX(c + 1);   // prefetch next chunk during MMA

#pragma unroll
        for (int s = 0; s < 4; s++) {
            const uint32_t kb = (uint32_t)(s * 32);
            uint32_t arh[2][4], arl[2][4];
#pragma unroll
            for (int t = 0; t < 2; t++) {
                uint32_t ah = sm_u + SM_XH + ((aoff[t] + kb) ^ xorv);
                asm volatile(
                    "ldmatrix.sync.aligned.m8n8.x4.shared.b16 {%0,%1,%2,%3}, [%4];"
                    : "=r"(arh[t][0]), "=r"(arh[t][1]), "=r"(arh[t][2]), "=r"(arh[t][3])
                    : "r"(ah));
                uint32_t al = sm_u + SM_XL + ((aoff[t] + kb) ^ xorv);
                asm volatile(
                    "ldmatrix.sync.aligned.m8n8.x4.shared.b16 {%0,%1,%2,%3}, [%4];"
                    : "=r"(arl[t][0]), "=r"(arl[t][1]), "=r"(arl[t][2]), "=r"(arl[t][3])
                    : "r"(al));
            }
#pragma unroll
            for (int half = 0; half < 2; half++) {
                uint32_t brh[4][4], brl[4][4];
#pragma unroll
                for (int u = 0; u < 4; u++) {
                    int jj = half * 4 + u;
                    uint32_t bh = sm_u + SM_WH + ((boff[jj] + kb) ^ xorv);
                    asm volatile(
                        "ldmatrix.sync.aligned.m8n8.x4.shared.b16 {%0,%1,%2,%3}, [%4];"
                        : "=r"(brh[u][0]), "=r"(brh[u][1]), "=r"(brh[u][2]), "=r"(brh[u][3])
                        : "r"(bh));
                    uint32_t bl = sm_u + SM_WL + ((boff[jj] + kb) ^ xorv);
                    asm volatile(
                        "ldmatrix.sync.aligned.m8n8.x4.shared.b16 {%0,%1,%2,%3}, [%4];"
                        : "=r"(brl[u][0]), "=r"(brl[u][1]), "=r"(brl[u][2]), "=r"(brl[u][3])
                        : "r"(bl));
                }
#pragma unroll
                for (int t = 0; t < 2; t++)
#pragma unroll
                    for (int jl = 0; jl < 8; jl++) {
                        const int j = half * 8 + jl;
                        const int u = jl >> 1, h = jl & 1;
                        // term 1: Xh * Wh
                        asm volatile(
                            "mma.sync.aligned.m16n8k16.row.col.f32.bf16.bf16.f32 "
                            "{%0,%1,%2,%3}, {%4,%5,%6,%7}, {%8,%9}, {%0,%1,%2,%3};"
                            : "+f"(acc[t][j][0]), "+f"(acc[t][j][1]),
                              "+f"(acc[t][j][2]), "+f"(acc[t][j][3])
                            : "r"(arh[t][0]), "r"(arh[t][1]), "r"(arh[t][2]), "r"(arh[t][3]),
                              "r"(brh[u][h]), "r"(brh[u][2 + h]));
                        // term 2: Xh * Wl
                        asm volatile(
                            "mma.sync.aligned.m16n8k16.row.col.f32.bf16.bf16.f32 "
                            "{%0,%1,%2,%3}, {%4,%5,%6,%7}, {%8,%9}, {%0,%1,%2,%3};"
                            : "+f"(acc[t][j][0]), "+f"(acc[t][j][1]),
                              "+f"(acc[t][j][2]), "+f"(acc[t][j][3])
                            : "r"(arh[t][0]), "r"(arh[t][1]), "r"(arh[t][2]), "r"(arh[t][3]),
                              "r"(brl[u][h]), "r"(brl[u][2 + h]));
                        // term 3: Xl * Wh
                        asm volatile(
                            "mma.sync.aligned.m16n8k16.row.col.f32.bf16.bf16.f32 "
                            "{%0,%1,%2,%3}, {%4,%5,%6,%7}, {%8,%9}, {%0,%1,%2,%3};"
                            : "+f"(acc[t][j][0]), "+f"(acc[t][j][1]),
                              "+f"(acc[t][j][2]), "+f"(acc[t][j][3])
                            : "r"(arl[t][0]), "r"(arl[t][1]), "r"(arl[t][2]), "r"(arl[t][3]),
                              "r"(brh[u][h]), "r"(brh[u][2 + h]));
                    }
            }
        }
    }

    // epilogue: C frags + bias -> g_H
    const int r0 = lane >> 2;
    const int c2 = (lane & 3) * 2;
#pragma unroll
    for (int t = 0; t < 2; t++) {
        int row = mbase + wm * 32 + t * 16 + r0;
#pragma unroll
        for (int j = 0; j < 16; j++) {
            int col = wn * 128 + j * 8 + c2;
            float2 bv = *(const float2*)(bias + col);
            if (row < NV) {
                float2 o;
                o.x = acc[t][j][0] + bv.x;
                o.y = acc[t][j][1] + bv.y;
                *(float2*)(g_H + (size_t)row * D + col) = o;
            }
            if (row + 8 < NV) {
                float2 o;
                o.x = acc[t][j][2] + bv.x;
                o.y = acc[t][j][3] + bv.y;
                *(float2*)(g_H + (size_t)(row + 8) * D + col) = o;
            }
        }
    }
#undef LOADX
}

// ---------------- v2e mean: pull member H rows, 8-wide MLP -------------------
__global__ __launch_bounds__(256) void k_v2e() {
    const int g    = threadIdx.x >> 6;
    const int lane = threadIdx.x & 63;
    const int e    = blockIdx.x * 4 + g;
    if (e >= NE) return;

    const int n = g_ecnt[e];
    const int m = min(n, CAPE);
    const int* __restrict__ sl = g_eslot + e * CAPE;
    const int off = lane * 4;

    float4 acc = make_float4(0.f, 0.f, 0.f, 0.f);
    int i = 0;
    for (; i + 8 <= m; i += 8) {
        int v0 = sl[i], v1 = sl[i+1], v2 = sl[i+2], v3 = sl[i+3];
        int v4 = sl[i+4], v5 = sl[i+5], v6 = sl[i+6], v7 = sl[i+7];
        float4 f0 = *(const float4*)(g_H + (size_t)v0 * D + off);
        float4 f1 = *(const float4*)(g_H + (size_t)v1 * D + off);
        float4 f2 = *(const float4*)(g_H + (size_t)v2 * D + off);
        float4 f3 = *(const float4*)(g_H + (size_t)v3 * D + off);
        float4 f4 = *(const float4*)(g_H + (size_t)v4 * D + off);
        float4 f5 = *(const float4*)(g_H + (size_t)v5 * D + off);
        float4 f6 = *(const float4*)(g_H + (size_t)v6 * D + off);
        float4 f7 = *(const float4*)(g_H + (size_t)v7 * D + off);
        acc.x += ((f0.x + f1.x) + (f2.x + f3.x)) + ((f4.x + f5.x) + (f6.x + f7.x));
        acc.y += ((f0.y + f1.y) + (f2.y + f3.y)) + ((f4.y + f5.y) + (f6.y + f7.y));
        acc.z += ((f0.z + f1.z) + (f2.z + f3.z)) + ((f4.z + f5.z) + (f6.z + f7.z));
        acc.w += ((f0.w + f1.w) + (f2.w + f3.w)) + ((f4.w + f5.w) + (f6.w + f7.w));
    }
    for (; i < m; i++) {
        int v = sl[i];
        float4 f = *(const float4*)(g_H + (size_t)v * D + off);
        acc.x += f.x; acc.y += f.y; acc.z += f.z; acc.w += f.w;
    }
    float inv = 1.f / (float)max(n, 1);
    float4 o = make_float4(acc.x * inv, acc.y * inv, acc.z * inv, acc.w * inv);
    *(float4*)(g_ef + (size_t)e * D + off) = o;
}

// ---------------- e2v mean + leaky relu, writes d_out ------------------------
__global__ __launch_bounds__(256) void k_e2v(float* __restrict__ out) {
    const int g    = threadIdx.x >> 6;
    const int lane = threadIdx.x & 63;
    const int v    = blockIdx.x * 4 + g;
    if (v >= NV) return;

    const int n = g_vcnt[v];
    const int m = min(n, CAPV);
    const int* __restrict__ sl = g_vslot + v * CAPV;
    const int off = lane * 4;

    float4 acc = make_float4(0.f, 0.f, 0.f, 0.f);
    int i = 0;
    for (; i + 8 <= m; i += 8) {
        int e0 = sl[i], e1 = sl[i+1], e2 = sl[i+2], e3 = sl[i+3];
        int e4 = sl[i+4], e5 = sl[i+5], e6 = sl[i+6], e7 = sl[i+7];
        float4 f0 = *(const float4*)(g_ef + (size_t)e0 * D + off);
        float4 f1 = *(const float4*)(g_ef + (size_t)e1 * D + off);
        float4 f2 = *(const float4*)(g_ef + (size_t)e2 * D + off);
        float4 f3 = *(const float4*)(g_ef + (size_t)e3 * D + off);
        float4 f4 = *(const float4*)(g_ef + (size_t)e4 * D + off);
        float4 f5 = *(const float4*)(g_ef + (size_t)e5 * D + off);
        float4 f6 = *(const float4*)(g_ef + (size_t)e6 * D + off);
        float4 f7 = *(const float4*)(g_ef + (size_t)e7 * D + off);
        acc.x += ((f0.x + f1.x) + (f2.x + f3.x)) + ((f4.x + f5.x) + (f6.x + f7.x));
        acc.y += ((f0.y + f1.y) + (f2.y + f3.y)) + ((f4.y + f5.y) + (f6.y + f7.y));
        acc.z += ((f0.z + f1.z) + (f2.z + f3.z)) + ((f4.z + f5.z) + (f6.z + f7.z));
        acc.w += ((f0.w + f1.w) + (f2.w + f3.w)) + ((f4.w + f5.w) + (f6.w + f7.w));
    }
    for (; i < m; i++) {
        int e = sl[i];
        float4 f = *(const float4*)(g_ef + (size_t)e * D + off);
        acc.x += f.x; acc.y += f.y; acc.z += f.z; acc.w += f.w;
    }
    float inv = 1.f / (float)max(n, 1);
    float4 o;
    float x;
    x = acc.x * inv; o.x = (x >= 0.f) ? x : 0.01f * x;
    x = acc.y * inv; o.y = (x >= 0.f) ? x : 0.01f * x;
    x = acc.z * inv; o.z = (x >= 0.f) ? x : 0.01f * x;
    x = acc.w * inv; o.w = (x >= 0.f) ? x : 0.01f * x;
    *(float4*)(out + (size_t)v * D + off) = o;
}

// ---------------- launch -----------------------------------------------------
extern "C" void kernel_launch(void* const* d_in, const int* in_sizes, int n_in,
                              void* d_out, int out_size) {
    const float* X     = (const float*)d_in[0];
    const float* W     = (const float*)d_in[1];
    const float* bias  = (const float*)d_in[2];
    const int*   v_idx = (const int*)d_in[3];
    const int*   e_idx = (const int*)d_in[4];
    float* out = (float*)d_out;

    cudaFuncSetAttribute(k_gemm, cudaFuncAttributeMaxDynamicSharedMemorySize,
                         SMEM_BYTES);

    k_init<<<256, 256>>>(W);                       // zero counters + split W
    k_build<<<(NP + 255) / 256, 256>>>(v_idx, e_idx);

    k_gemm<<<(NV + MT - 1) / MT, 256, SMEM_BYTES>>>(X, bias);   // 391 CTAs

    k_v2e<<<(NE + 3) / 4, 256>>>();
    k_e2v<<<(NV + 3) / 4, 256>>>(out);
}

// round 8
// speedup vs baseline: 1.5710x; 1.1401x over previous
#include <cuda_runtime.h>
#include <cuda_bf16.h>
#include <cuda_fp16.h>
#include <cstdint>

#define NV 50000
#define NE 10000
#define NP 800000
#define D  256
#define CAPE 192
#define CAPV 64

// ---------------- device scratch (no runtime allocation allowed) -----------
__device__ __half g_H[NV * D];                // 25.6 MB projected vertex features (fp16)
__device__ __half g_ef[NE * D];               // 5.1 MB  hyperedge features (fp16)
__device__ int    g_ecnt[NE];
__device__ int    g_vcnt[NV];
__device__ int    g_eslot[NE * CAPE];
__device__ int    g_vslot[NV * CAPV];
__device__ __nv_bfloat16 g_Wth[D * D];        // W^T hi  [n][k]
__device__ __nv_bfloat16 g_Wtl[D * D];        // W^T lo  [n][k]

__device__ __forceinline__ uint32_t smem_u32(const void* p) {
    uint32_t a;
    asm("{ .reg .u64 t; cvta.to.shared.u64 t, %1; cvt.u32.u64 %0, t; }"
        : "=r"(a) : "l"(p));
    return a;
}

// ---------------- init: zero counters + split/transpose W -------------------
__global__ void k_init(const float* __restrict__ W) {
    int i = blockIdx.x * blockDim.x + threadIdx.x;   // 65536 threads
    if (i < NE) g_ecnt[i] = 0;
    if (i < NV) g_vcnt[i] = 0;
    int k = i >> 8, n = i & 255;
    float w = W[k * D + n];
    __nv_bfloat16 h = __float2bfloat16(w);
    __nv_bfloat16 l = __float2bfloat16(w - __bfloat162float(h));
    g_Wth[n * D + k] = h;
    g_Wtl[n * D + k] = l;
}

// ---------------- build inverted slot lists (2 pairs / thread) --------------
__global__ void k_build(const int* __restrict__ v_idx,
                        const int* __restrict__ e_idx) {
    int i = blockIdx.x * blockDim.x + threadIdx.x;
    if (i >= NP / 2) return;
    int2 vv = ((const int2*)v_idx)[i];
    int2 ee = ((const int2*)e_idx)[i];
#pragma unroll
    for (int t = 0; t < 2; t++) {
        int v = t ? vv.y : vv.x;
        int e = t ? ee.y : ee.x;
        int pe = atomicAdd(&g_ecnt[e], 1);
        if (pe < CAPE) g_eslot[e * CAPE + pe] = v;
        int pv = atomicAdd(&g_vcnt[v], 1);
        if (pv < CAPV) g_vslot[v * CAPV + pv] = e;
    }
}

// ---------------- fused split + bf16-split GEMM (HMMA): H = X*W + b ---------
// CTA tile 128x256, 8 warps (4 M x 2 N), warp tile 32x128. fp16 output.
#define MT 128
#define KC 64
#define SM_XH 0
#define SM_XL (16 * 1024)
#define SM_WH (32 * 1024)
#define SM_WL (64 * 1024)
#define SMEM_BYTES (96 * 1024)

extern __shared__ __align__(1024) char dynsm[];

__global__ __launch_bounds__(256, 1) void k_gemm(const float* __restrict__ X,
                                                 const float* __restrict__ bias) {
    char* sm = dynsm;
    const int tid  = threadIdx.x;
    const int wid  = tid >> 5;
    const int lane = tid & 31;
    const int mbase = blockIdx.x * MT;
    const int wm = wid & 3;
    const int wn = wid >> 2;

    const uint32_t sm_u = smem_u32(sm);
    const uint32_t xorv = (uint32_t)(lane & 7) << 4;

    uint32_t aoff[2], boff[8];
#pragma unroll
    for (int t = 0; t < 2; t++)
        aoff[t] = (uint32_t)((wm * 32 + t * 16 + (lane & 15)) * 128 + (lane >> 4) * 16);
#pragma unroll
    for (int jj = 0; jj < 8; jj++)
        boff[jj] = (uint32_t)((wn * 128 + jj * 16 + (lane & 15)) * 128 + (lane >> 4) * 16);

    const int rt  = tid >> 3;
    const int seg = tid & 7;

    float acc[2][16][4];
#pragma unroll
    for (int t = 0; t < 2; t++)
#pragma unroll
        for (int j = 0; j < 16; j++)
#pragma unroll
            for (int q = 0; q < 4; q++) acc[t][j][q] = 0.f;

    float4 pf[8];

#define LOADX(c) do {                                                          \
    int kc = (c) * KC;                                                         \
    _Pragma("unroll")                                                          \
    for (int q = 0; q < 4; q++) {                                              \
        int gr = mbase + 32 * q + rt;                                          \
        if (gr < NV) {                                                         \
            const float* p = X + (size_t)gr * D + kc + seg * 8;                \
            pf[2 * q]     = *(const float4*)(p);                               \
            pf[2 * q + 1] = *(const float4*)(p + 4);                           \
        } else {                                                               \
            pf[2 * q] = pf[2 * q + 1] = make_float4(0.f, 0.f, 0.f, 0.f);       \
        }                                                                      \
    } } while (0)

    LOADX(0);

    for (int c = 0; c < 4; c++) {
        if (c > 0) __syncthreads();
#pragma unroll
        for (int q = 0; q < 4; q++) {
            int r = 32 * q + rt;
            uint32_t off = (uint32_t)(r * 128 + seg * 16);
            uint32_t sw  = off ^ (uint32_t)((r & 7) << 4);
            float f[8];
            f[0]=pf[2*q].x; f[1]=pf[2*q].y; f[2]=pf[2*q].z; f[3]=pf[2*q].w;
            f[4]=pf[2*q+1].x; f[5]=pf[2*q+1].y; f[6]=pf[2*q+1].z; f[7]=pf[2*q+1].w;
            uint32_t hw[4], lw[4];
#pragma unroll
            for (int p2 = 0; p2 < 4; p2++) {
                __nv_bfloat16 h0 = __float2bfloat16(f[2*p2]);
                __nv_bfloat16 h1 = __float2bfloat16(f[2*p2+1]);
                __nv_bfloat16 l0 = __float2bfloat16(f[2*p2]   - __bfloat162float(h0));
                __nv_bfloat16 l1 = __float2bfloat16(f[2*p2+1] - __bfloat162float(h1));
                hw[p2] = ((uint32_t)__bfloat16_as_ushort(h1) << 16) | __bfloat16_as_ushort(h0);
                lw[p2] = ((uint32_t)__bfloat16_as_ushort(l1) << 16) | __bfloat16_as_ushort(l0);
            }
            *(uint4*)(sm + SM_XH + sw) = make_uint4(hw[0], hw[1], hw[2], hw[3]);
            *(uint4*)(sm + SM_XL + sw) = make_uint4(lw[0], lw[1], lw[2], lw[3]);
        }
        {
            int kc = c * KC;
#pragma unroll
            for (int q = 0; q < 8; q++) {
                int n = 32 * q + rt;
                uint32_t off = (uint32_t)(n * 128 + seg * 16);
                uint32_t sw  = off ^ (uint32_t)((n & 7) << 4);
                uint4 hv = *(const uint4*)(g_Wth + (size_t)n * D + kc + seg * 8);
                uint4 lv = *(const uint4*)(g_Wtl + (size_t)n * D + kc + seg * 8);
                *(uint4*)(sm + SM_WH + sw) = hv;
                *(uint4*)(sm + SM_WL + sw) = lv;
            }
        }
        __syncthreads();
        if (c < 3) LOADX(c + 1);

#pragma unroll
        for (int s = 0; s < 4; s++) {
            const uint32_t kb = (uint32_t)(s * 32);
            uint32_t arh[2][4], arl[2][4];
#pragma unroll
            for (int t = 0; t < 2; t++) {
                uint32_t ah = sm_u + SM_XH + ((aoff[t] + kb) ^ xorv);
                asm volatile(
                    "ldmatrix.sync.aligned.m8n8.x4.shared.b16 {%0,%1,%2,%3}, [%4];"
                    : "=r"(arh[t][0]), "=r"(arh[t][1]), "=r"(arh[t][2]), "=r"(arh[t][3])
                    : "r"(ah));
                uint32_t al = sm_u + SM_XL + ((aoff[t] + kb) ^ xorv);
                asm volatile(
                    "ldmatrix.sync.aligned.m8n8.x4.shared.b16 {%0,%1,%2,%3}, [%4];"
                    : "=r"(arl[t][0]), "=r"(arl[t][1]), "=r"(arl[t][2]), "=r"(arl[t][3])
                    : "r"(al));
            }
#pragma unroll
            for (int half = 0; half < 2; half++) {
                uint32_t brh[4][4], brl[4][4];
#pragma unroll
                for (int u = 0; u < 4; u++) {
                    int jj = half * 4 + u;
                    uint32_t bh = sm_u + SM_WH + ((boff[jj] + kb) ^ xorv);
                    asm volatile(
                        "ldmatrix.sync.aligned.m8n8.x4.shared.b16 {%0,%1,%2,%3}, [%4];"
                        : "=r"(brh[u][0]), "=r"(brh[u][1]), "=r"(brh[u][2]), "=r"(brh[u][3])
                        : "r"(bh));
                    uint32_t bl = sm_u + SM_WL + ((boff[jj] + kb) ^ xorv);
                    asm volatile(
                        "ldmatrix.sync.aligned.m8n8.x4.shared.b16 {%0,%1,%2,%3}, [%4];"
                        : "=r"(brl[u][0]), "=r"(brl[u][1]), "=r"(brl[u][2]), "=r"(brl[u][3])
                        : "r"(bl));
                }
#pragma unroll
                for (int t = 0; t < 2; t++)
#pragma unroll
                    for (int jl = 0; jl < 8; jl++) {
                        const int j = half * 8 + jl;
                        const int u = jl >> 1, h = jl & 1;
                        asm volatile(
                            "mma.sync.aligned.m16n8k16.row.col.f32.bf16.bf16.f32 "
                            "{%0,%1,%2,%3}, {%4,%5,%6,%7}, {%8,%9}, {%0,%1,%2,%3};"
                            : "+f"(acc[t][j][0]), "+f"(acc[t][j][1]),
                              "+f"(acc[t][j][2]), "+f"(acc[t][j][3])
                            : "r"(arh[t][0]), "r"(arh[t][1]), "r"(arh[t][2]), "r"(arh[t][3]),
                              "r"(brh[u][h]), "r"(brh[u][2 + h]));
                        asm volatile(
                            "mma.sync.aligned.m16n8k16.row.col.f32.bf16.bf16.f32 "
                            "{%0,%1,%2,%3}, {%4,%5,%6,%7}, {%8,%9}, {%0,%1,%2,%3};"
                            : "+f"(acc[t][j][0]), "+f"(acc[t][j][1]),
                              "+f"(acc[t][j][2]), "+f"(acc[t][j][3])
                            : "r"(arh[t][0]), "r"(arh[t][1]), "r"(arh[t][2]), "r"(arh[t][3]),
                              "r"(brl[u][h]), "r"(brl[u][2 + h]));
                        asm volatile(
                            "mma.sync.aligned.m16n8k16.row.col.f32.bf16.bf16.f32 "
                            "{%0,%1,%2,%3}, {%4,%5,%6,%7}, {%8,%9}, {%0,%1,%2,%3};"
                            : "+f"(acc[t][j][0]), "+f"(acc[t][j][1]),
                              "+f"(acc[t][j][2]), "+f"(acc[t][j][3])
                            : "r"(arl[t][0]), "r"(arl[t][1]), "r"(arl[t][2]), "r"(arl[t][3]),
                              "r"(brh[u][h]), "r"(brh[u][2 + h]));
                    }
            }
        }
    }

    // epilogue: C frags + bias -> g_H (fp16)
    const int r0 = lane >> 2;
    const int c2 = (lane & 3) * 2;
#pragma unroll
    for (int t = 0; t < 2; t++) {
        int row = mbase + wm * 32 + t * 16 + r0;
#pragma unroll
        for (int j = 0; j < 16; j++) {
            int col = wn * 128 + j * 8 + c2;
            float2 bv = *(const float2*)(bias + col);
            if (row < NV) {
                __half2 o = __floats2half2_rn(acc[t][j][0] + bv.x,
                                              acc[t][j][1] + bv.y);
                *(__half2*)(g_H + (size_t)row * D + col) = o;
            }
            if (row + 8 < NV) {
                __half2 o = __floats2half2_rn(acc[t][j][2] + bv.x,
                                              acc[t][j][3] + bv.y);
                *(__half2*)(g_H + (size_t)(row + 8) * D + col) = o;
            }
        }
    }
#undef LOADX
}

// ---------------- v2e mean: fp16 gather, fp32 accum --------------------------
// 8 edges per 256-thread block; 32 lanes per edge, lane owns 8 dims (uint4)
__global__ __launch_bounds__(256) void k_v2e() {
    const int g    = threadIdx.x >> 5;
    const int lane = threadIdx.x & 31;
    const int e    = blockIdx.x * 8 + g;
    if (e >= NE) return;

    const int n = g_ecnt[e];
    const int m = min(n, CAPE);
    const int* __restrict__ sl = g_eslot + e * CAPE;
    const int off = lane * 8;

    float acc[8];
#pragma unroll
    for (int q = 0; q < 8; q++) acc[q] = 0.f;

    int i = 0;
    for (; i + 8 <= m; i += 8) {
        uint4 u[8];
#pragma unroll
        for (int r = 0; r < 8; r++) {
            int v = sl[i + r];
            u[r] = *(const uint4*)(g_H + (size_t)v * D + off);
        }
#pragma unroll
        for (int r = 0; r < 8; r++) {
            float2 a = __half22float2(*(__half2*)&u[r].x);
            float2 b = __half22float2(*(__half2*)&u[r].y);
            float2 c = __half22float2(*(__half2*)&u[r].z);
            float2 d = __half22float2(*(__half2*)&u[r].w);
            acc[0] += a.x; acc[1] += a.y; acc[2] += b.x; acc[3] += b.y;
            acc[4] += c.x; acc[5] += c.y; acc[6] += d.x; acc[7] += d.y;
        }
    }
    for (; i < m; i++) {
        int v = sl[i];
        uint4 u = *(const uint4*)(g_H + (size_t)v * D + off);
        float2 a = __half22float2(*(__half2*)&u.x);
        float2 b = __half22float2(*(__half2*)&u.y);
        float2 c = __half22float2(*(__half2*)&u.z);
        float2 d = __half22float2(*(__half2*)&u.w);
        acc[0] += a.x; acc[1] += a.y; acc[2] += b.x; acc[3] += b.y;
        acc[4] += c.x; acc[5] += c.y; acc[6] += d.x; acc[7] += d.y;
    }
    float inv = 1.f / (float)max(n, 1);
    uint4 o;
    ((__half2*)&o.x)[0] = __floats2half2_rn(acc[0] * inv, acc[1] * inv);
    ((__half2*)&o.y)[0] = __floats2half2_rn(acc[2] * inv, acc[3] * inv);
    ((__half2*)&o.z)[0] = __floats2half2_rn(acc[4] * inv, acc[5] * inv);
    ((__half2*)&o.w)[0] = __floats2half2_rn(acc[6] * inv, acc[7] * inv);
    *(uint4*)(g_ef + (size_t)e * D + off) = o;
}

// ---------------- e2v mean + leaky relu, fp32 out ----------------------------
__global__ __launch_bounds__(256) void k_e2v(float* __restrict__ out) {
    const int g    = threadIdx.x >> 5;
    const int lane = threadIdx.x & 31;
    const int v    = blockIdx.x * 8 + g;
    if (v >= NV) return;

    const int n = g_vcnt[v];
    const int m = min(n, CAPV);
    const int* __restrict__ sl = g_vslot + v * CAPV;
    const int off = lane * 8;

    float acc[8];
#pragma unroll
    for (int q = 0; q < 8; q++) acc[q] = 0.f;

    int i = 0;
    for (; i + 8 <= m; i += 8) {
        uint4 u[8];
#pragma unroll
        for (int r = 0; r < 8; r++) {
            int e = sl[i + r];
            u[r] = *(const uint4*)(g_ef + (size_t)e * D + off);
        }
#pragma unroll
        for (int r = 0; r < 8; r++) {
            float2 a = __half22float2(*(__half2*)&u[r].x);
            float2 b = __half22float2(*(__half2*)&u[r].y);
            float2 c = __half22float2(*(__half2*)&u[r].z);
            float2 d = __half22float2(*(__half2*)&u[r].w);
            acc[0] += a.x; acc[1] += a.y; acc[2] += b.x; acc[3] += b.y;
            acc[4] += c.x; acc[5] += c.y; acc[6] += d.x; acc[7] += d.y;
        }
    }
    for (; i < m; i++) {
        int e = sl[i];
        uint4 u = *(const uint4*)(g_ef + (size_t)e * D + off);
        float2 a = __half22float2(*(__half2*)&u.x);
        float2 b = __half22float2(*(__half2*)&u.y);
        float2 c = __half22float2(*(__half2*)&u.z);
        float2 d = __half22float2(*(__half2*)&u.w);
        acc[0] += a.x; acc[1] += a.y; acc[2] += b.x; acc[3] += b.y;
        acc[4] += c.x; acc[5] += c.y; acc[6] += d.x; acc[7] += d.y;
    }
    float inv = 1.f / (float)max(n, 1);
    float4 o0, o1;
    float x;
    x = acc[0] * inv; o0.x = (x >= 0.f) ? x : 0.01f * x;
    x = acc[1] * inv; o0.y = (x >= 0.f) ? x : 0.01f * x;
    x = acc[2] * inv; o0.z = (x >= 0.f) ? x : 0.01f * x;
    x = acc[3] * inv; o0.w = (x >= 0.f) ? x : 0.01f * x;
    x = acc[4] * inv; o1.x = (x >= 0.f) ? x : 0.01f * x;
    x = acc[5] * inv; o1.y = (x >= 0.f) ? x : 0.01f * x;
    x = acc[6] * inv; o1.z = (x >= 0.f) ? x : 0.01f * x;
    x = acc[7] * inv; o1.w = (x >= 0.f) ? x : 0.01f * x;
    float* op = out + (size_t)v * D + off;
    *(float4*)(op)     = o0;
    *(float4*)(op + 4) = o1;
}

// ---------------- launch -----------------------------------------------------
extern "C" void kernel_launch(void* const* d_in, const int* in_sizes, int n_in,
                              void* d_out, int out_size) {
    const float* X     = (const float*)d_in[0];
    const float* W     = (const float*)d_in[1];
    const float* bias  = (const float*)d_in[2];
    const int*   v_idx = (const int*)d_in[3];
    const int*   e_idx = (const int*)d_in[4];
    float* out = (float*)d_out;

    cudaFuncSetAttribute(k_gemm, cudaFuncAttributeMaxDynamicSharedMemorySize,
                         SMEM_BYTES);

    k_init<<<256, 256>>>(W);
    k_build<<<(NP / 2 + 255) / 256, 256>>>(v_idx, e_idx);

    k_gemm<<<(NV + MT - 1) / MT, 256, SMEM_BYTES>>>(X, bias);

    k_v2e<<<(NE + 7) / 8, 256>>>();
    k_e2v<<<(NV + 7) / 8, 256>>>(out);
}

// round 9
// speedup vs baseline: 1.6407x; 1.0444x over previous
#include <cuda_runtime.h>
#include <cuda_bf16.h>
#include <cuda_fp16.h>
#include <cstdint>

#define NV 50000
#define NE 10000
#define NP 800000
#define D  256
#define CAPE 192
#define CAPV 64

// ---------------- device scratch (no runtime allocation allowed) -----------
__device__ __half g_H[NV * D];                // 25.6 MB projected vertex features (fp16)
__device__ __half g_ef[NE * D];               // 5.1 MB  hyperedge features (fp16)
__device__ int    g_ecnt[NE];
__device__ int    g_vcnt[NV];
__device__ int    g_eslot[NE * CAPE];
__device__ int    g_vslot[NV * CAPV];
__device__ __nv_bfloat16 g_Wth[D * D];        // W^T hi  [n][k]
__device__ __nv_bfloat16 g_Wtl[D * D];        // W^T lo  [n][k]

__device__ __forceinline__ uint32_t smem_u32(const void* p) {
    uint32_t a;
    asm("{ .reg .u64 t; cvta.to.shared.u64 t, %1; cvt.u32.u64 %0, t; }"
        : "=r"(a) : "l"(p));
    return a;
}

// ---------------- init: zero counters + split/transpose W -------------------
__global__ void k_init(const float* __restrict__ W) {
    int i = blockIdx.x * blockDim.x + threadIdx.x;   // 65536 threads
    if (i < NE) g_ecnt[i] = 0;
    if (i < NV) g_vcnt[i] = 0;
    int k = i >> 8, n = i & 255;
    float w = W[k * D + n];
    __nv_bfloat16 h = __float2bfloat16(w);
    __nv_bfloat16 l = __float2bfloat16(w - __bfloat162float(h));
    g_Wth[n * D + k] = h;
    g_Wtl[n * D + k] = l;
}

// ---------------- build inverted slot lists (2 pairs / thread) --------------
__global__ void k_build(const int* __restrict__ v_idx,
                        const int* __restrict__ e_idx) {
    int i = blockIdx.x * blockDim.x + threadIdx.x;
    if (i >= NP / 2) return;
    int2 vv = ((const int2*)v_idx)[i];
    int2 ee = ((const int2*)e_idx)[i];
#pragma unroll
    for (int t = 0; t < 2; t++) {
        int v = t ? vv.y : vv.x;
        int e = t ? ee.y : ee.x;
        int pe = atomicAdd(&g_ecnt[e], 1);
        if (pe < CAPE) g_eslot[e * CAPE + pe] = v;
        int pv = atomicAdd(&g_vcnt[v], 1);
        if (pv < CAPV) g_vslot[v * CAPV + pv] = e;
    }
}

// ---------------- fused split + bf16-split GEMM (HMMA): H = X*W + b ---------
#define MT 128
#define KC 64
#define SM_XH 0
#define SM_XL (16 * 1024)
#define SM_WH (32 * 1024)
#define SM_WL (64 * 1024)
#define SMEM_BYTES (96 * 1024)

extern __shared__ __align__(1024) char dynsm[];

__global__ __launch_bounds__(256, 1) void k_gemm(const float* __restrict__ X,
                                                 const float* __restrict__ bias) {
    char* sm = dynsm;
    const int tid  = threadIdx.x;
    const int wid  = tid >> 5;
    const int lane = tid & 31;
    const int mbase = blockIdx.x * MT;
    const int wm = wid & 3;
    const int wn = wid >> 2;

    const uint32_t sm_u = smem_u32(sm);
    const uint32_t xorv = (uint32_t)(lane & 7) << 4;

    uint32_t aoff[2], boff[8];
#pragma unroll
    for (int t = 0; t < 2; t++)
        aoff[t] = (uint32_t)((wm * 32 + t * 16 + (lane & 15)) * 128 + (lane >> 4) * 16);
#pragma unroll
    for (int jj = 0; jj < 8; jj++)
        boff[jj] = (uint32_t)((wn * 128 + jj * 16 + (lane & 15)) * 128 + (lane >> 4) * 16);

    const int rt  = tid >> 3;
    const int seg = tid & 7;

    float acc[2][16][4];
#pragma unroll
    for (int t = 0; t < 2; t++)
#pragma unroll
        for (int j = 0; j < 16; j++)
#pragma unroll
            for (int q = 0; q < 4; q++) acc[t][j][q] = 0.f;

    float4 pf[8];

#define LOADX(c) do {                                                          \
    int kc = (c) * KC;                                                         \
    _Pragma("unroll")                                                          \
    for (int q = 0; q < 4; q++) {                                              \
        int gr = mbase + 32 * q + rt;                                          \
        if (gr < NV) {                                                         \
            const float* p = X + (size_t)gr * D + kc + seg * 8;                \
            pf[2 * q]     = *(const float4*)(p);                               \
            pf[2 * q + 1] = *(const float4*)(p + 4);                           \
        } else {                                                               \
            pf[2 * q] = pf[2 * q + 1] = make_float4(0.f, 0.f, 0.f, 0.f);       \
        }                                                                      \
    } } while (0)

    LOADX(0);

    for (int c = 0; c < 4; c++) {
        if (c > 0) __syncthreads();
#pragma unroll
        for (int q = 0; q < 4; q++) {
            int r = 32 * q + rt;
            uint32_t off = (uint32_t)(r * 128 + seg * 16);
            uint32_t sw  = off ^ (uint32_t)((r & 7) << 4);
            float f[8];
            f[0]=pf[2*q].x; f[1]=pf[2*q].y; f[2]=pf[2*q].z; f[3]=pf[2*q].w;
            f[4]=pf[2*q+1].x; f[5]=pf[2*q+1].y; f[6]=pf[2*q+1].z; f[7]=pf[2*q+1].w;
            uint32_t hw[4], lw[4];
#pragma unroll
            for (int p2 = 0; p2 < 4; p2++) {
                __nv_bfloat16 h0 = __float2bfloat16(f[2*p2]);
                __nv_bfloat16 h1 = __float2bfloat16(f[2*p2+1]);
                __nv_bfloat16 l0 = __float2bfloat16(f[2*p2]   - __bfloat162float(h0));
                __nv_bfloat16 l1 = __float2bfloat16(f[2*p2+1] - __bfloat162float(h1));
                hw[p2] = ((uint32_t)__bfloat16_as_ushort(h1) << 16) | __bfloat16_as_ushort(h0);
                lw[p2] = ((uint32_t)__bfloat16_as_ushort(l1) << 16) | __bfloat16_as_ushort(l0);
            }
            *(uint4*)(sm + SM_XH + sw) = make_uint4(hw[0], hw[1], hw[2], hw[3]);
            *(uint4*)(sm + SM_XL + sw) = make_uint4(lw[0], lw[1], lw[2], lw[3]);
        }
        {
            int kc = c * KC;
#pragma unroll
            for (int q = 0; q < 8; q++) {
                int n = 32 * q + rt;
                uint32_t off = (uint32_t)(n * 128 + seg * 16);
                uint32_t sw  = off ^ (uint32_t)((n & 7) << 4);
                uint4 hv = *(const uint4*)(g_Wth + (size_t)n * D + kc + seg * 8);
                uint4 lv = *(const uint4*)(g_Wtl + (size_t)n * D + kc + seg * 8);
                *(uint4*)(sm + SM_WH + sw) = hv;
                *(uint4*)(sm + SM_WL + sw) = lv;
            }
        }
        __syncthreads();
        if (c < 3) LOADX(c + 1);

#pragma unroll
        for (int s = 0; s < 4; s++) {
            const uint32_t kb = (uint32_t)(s * 32);
            uint32_t arh[2][4], arl[2][4];
#pragma unroll
            for (int t = 0; t < 2; t++) {
                uint32_t ah = sm_u + SM_XH + ((aoff[t] + kb) ^ xorv);
                asm volatile(
                    "ldmatrix.sync.aligned.m8n8.x4.shared.b16 {%0,%1,%2,%3}, [%4];"
                    : "=r"(arh[t][0]), "=r"(arh[t][1]), "=r"(arh[t][2]), "=r"(arh[t][3])
                    : "r"(ah));
                uint32_t al = sm_u + SM_XL + ((aoff[t] + kb) ^ xorv);
                asm volatile(
                    "ldmatrix.sync.aligned.m8n8.x4.shared.b16 {%0,%1,%2,%3}, [%4];"
                    : "=r"(arl[t][0]), "=r"(arl[t][1]), "=r"(arl[t][2]), "=r"(arl[t][3])
                    : "r"(al));
            }
#pragma unroll
            for (int half = 0; half < 2; half++) {
                uint32_t brh[4][4], brl[4][4];
#pragma unroll
                for (int u = 0; u < 4; u++) {
                    int jj = half * 4 + u;
                    uint32_t bh = sm_u + SM_WH + ((boff[jj] + kb) ^ xorv);
                    asm volatile(
                        "ldmatrix.sync.aligned.m8n8.x4.shared.b16 {%0,%1,%2,%3}, [%4];"
                        : "=r"(brh[u][0]), "=r"(brh[u][1]), "=r"(brh[u][2]), "=r"(brh[u][3])
                        : "r"(bh));
                    uint32_t bl = sm_u + SM_WL + ((boff[jj] + kb) ^ xorv);
                    asm volatile(
                        "ldmatrix.sync.aligned.m8n8.x4.shared.b16 {%0,%1,%2,%3}, [%4];"
                        : "=r"(brl[u][0]), "=r"(brl[u][1]), "=r"(brl[u][2]), "=r"(brl[u][3])
                        : "r"(bl));
                }
#pragma unroll
                for (int t = 0; t < 2; t++)
#pragma unroll
                    for (int jl = 0; jl < 8; jl++) {
                        const int j = half * 8 + jl;
                        const int u = jl >> 1, h = jl & 1;
                        asm volatile(
                            "mma.sync.aligned.m16n8k16.row.col.f32.bf16.bf16.f32 "
                            "{%0,%1,%2,%3}, {%4,%5,%6,%7}, {%8,%9}, {%0,%1,%2,%3};"
                            : "+f"(acc[t][j][0]), "+f"(acc[t][j][1]),
                              "+f"(acc[t][j][2]), "+f"(acc[t][j][3])
                            : "r"(arh[t][0]), "r"(arh[t][1]), "r"(arh[t][2]), "r"(arh[t][3]),
                              "r"(brh[u][h]), "r"(brh[u][2 + h]));
                        asm volatile(
                            "mma.sync.aligned.m16n8k16.row.col.f32.bf16.bf16.f32 "
                            "{%0,%1,%2,%3}, {%4,%5,%6,%7}, {%8,%9}, {%0,%1,%2,%3};"
                            : "+f"(acc[t][j][0]), "+f"(acc[t][j][1]),
                              "+f"(acc[t][j][2]), "+f"(acc[t][j][3])
                            : "r"(arh[t][0]), "r"(arh[t][1]), "r"(arh[t][2]), "r"(arh[t][3]),
                              "r"(brl[u][h]), "r"(brl[u][2 + h]));
                        asm volatile(
                            "mma.sync.aligned.m16n8k16.row.col.f32.bf16.bf16.f32 "
                            "{%0,%1,%2,%3}, {%4,%5,%6,%7}, {%8,%9}, {%0,%1,%2,%3};"
                            : "+f"(acc[t][j][0]), "+f"(acc[t][j][1]),
                              "+f"(acc[t][j][2]), "+f"(acc[t][j][3])
                            : "r"(arl[t][0]), "r"(arl[t][1]), "r"(arl[t][2]), "r"(arl[t][3]),
                              "r"(brh[u][h]), "r"(brh[u][2 + h]));
                    }
            }
        }
    }

    // epilogue: C frags + bias -> g_H (fp16)
    const int r0 = lane >> 2;
    const int c2 = (lane & 3) * 2;
#pragma unroll
    for (int t = 0; t < 2; t++) {
        int row = mbase + wm * 32 + t * 16 + r0;
#pragma unroll
        for (int j = 0; j < 16; j++) {
            int col = wn * 128 + j * 8 + c2;
            float2 bv = *(const float2*)(bias + col);
            if (row < NV) {
                __half2 o = __floats2half2_rn(acc[t][j][0] + bv.x,
                                              acc[t][j][1] + bv.y);
                *(__half2*)(g_H + (size_t)row * D + col) = o;
            }
            if (row + 8 < NV) {
                __half2 o = __floats2half2_rn(acc[t][j][2] + bv.x,
                                              acc[t][j][3] + bv.y);
                *(__half2*)(g_H + (size_t)(row + 8) * D + col) = o;
            }
        }
    }
#undef LOADX
}

// ---- helper: accumulate a half2-packed uint4 into 8 fp32 lanes --------------
__device__ __forceinline__ void acc_u4(float* acc, uint4 u) {
    float2 a = __half22float2(*(__half2*)&u.x);
    float2 b = __half22float2(*(__half2*)&u.y);
    float2 c = __half22float2(*(__half2*)&u.z);
    float2 d = __half22float2(*(__half2*)&u.w);
    acc[0] += a.x; acc[1] += a.y; acc[2] += b.x; acc[3] += b.y;
    acc[4] += c.x; acc[5] += c.y; acc[6] += d.x; acc[7] += d.y;
}
// pairwise fp16 add of two packed rows (4x HADD2)
__device__ __forceinline__ uint4 hadd_u4(uint4 p, uint4 q) {
    uint4 r;
    *(__half2*)&r.x = __hadd2(*(__half2*)&p.x, *(__half2*)&q.x);
    *(__half2*)&r.y = __hadd2(*(__half2*)&p.y, *(__half2*)&q.y);
    *(__half2*)&r.z = __hadd2(*(__half2*)&p.z, *(__half2*)&q.z);
    *(__half2*)&r.w = __hadd2(*(__half2*)&p.w, *(__half2*)&q.w);
    return r;
}

// ---------------- v2e mean: fp16 gather, pairwise fp16 + fp32 accum ----------
__global__ __launch_bounds__(256) void k_v2e() {
    const int g    = threadIdx.x >> 5;
    const int lane = threadIdx.x & 31;
    const int e    = blockIdx.x * 8 + g;
    if (e >= NE) return;

    const int n = g_ecnt[e];
    const int m = min(n, CAPE);
    const int* __restrict__ sl = g_eslot + e * CAPE;
    const int off = lane * 8;

    float acc[8];
#pragma unroll
    for (int q = 0; q < 8; q++) acc[q] = 0.f;

    int i = 0;
    for (; i + 8 <= m; i += 8) {
        int4 i0 = *(const int4*)(sl + i);
        int4 i1 = *(const int4*)(sl + i + 4);
        uint4 u0 = *(const uint4*)(g_H + (size_t)i0.x * D + off);
        uint4 u1 = *(const uint4*)(g_H + (size_t)i0.y * D + off);
        uint4 u2 = *(const uint4*)(g_H + (size_t)i0.z * D + off);
        uint4 u3 = *(const uint4*)(g_H + (size_t)i0.w * D + off);
        uint4 u4 = *(const uint4*)(g_H + (size_t)i1.x * D + off);
        uint4 u5 = *(const uint4*)(g_H + (size_t)i1.y * D + off);
        uint4 u6 = *(const uint4*)(g_H + (size_t)i1.z * D + off);
        uint4 u7 = *(const uint4*)(g_H + (size_t)i1.w * D + off);
        acc_u4(acc, hadd_u4(u0, u1));
        acc_u4(acc, hadd_u4(u2, u3));
        acc_u4(acc, hadd_u4(u4, u5));
        acc_u4(acc, hadd_u4(u6, u7));
    }
    for (; i < m; i++) {
        int v = sl[i];
        acc_u4(acc, *(const uint4*)(g_H + (size_t)v * D + off));
    }
    float inv = 1.f / (float)max(n, 1);
    uint4 o;
    ((__half2*)&o.x)[0] = __floats2half2_rn(acc[0] * inv, acc[1] * inv);
    ((__half2*)&o.y)[0] = __floats2half2_rn(acc[2] * inv, acc[3] * inv);
    ((__half2*)&o.z)[0] = __floats2half2_rn(acc[4] * inv, acc[5] * inv);
    ((__half2*)&o.w)[0] = __floats2half2_rn(acc[6] * inv, acc[7] * inv);
    *(uint4*)(g_ef + (size_t)e * D + off) = o;
}

// ---------------- e2v mean + leaky relu, fp32 out ----------------------------
__global__ __launch_bounds__(256) void k_e2v(float* __restrict__ out) {
    const int g    = threadIdx.x >> 5;
    const int lane = threadIdx.x & 31;
    const int v    = blockIdx.x * 8 + g;
    if (v >= NV) return;

    const int n = g_vcnt[v];
    const int m = min(n, CAPV);
    const int* __restrict__ sl = g_vslot + v * CAPV;
    const int off = lane * 8;

    float acc[8];
#pragma unroll
    for (int q = 0; q < 8; q++) acc[q] = 0.f;

    int i = 0;
    for (; i + 8 <= m; i += 8) {
        int4 i0 = *(const int4*)(sl + i);
        int4 i1 = *(const int4*)(sl + i + 4);
        uint4 u0 = *(const uint4*)(g_ef + (size_t)i0.x * D + off);
        uint4 u1 = *(const uint4*)(g_ef + (size_t)i0.y * D + off);
        uint4 u2 = *(const uint4*)(g_ef + (size_t)i0.z * D + off);
        uint4 u3 = *(const uint4*)(g_ef + (size_t)i0.w * D + off);
        uint4 u4 = *(const uint4*)(g_ef + (size_t)i1.x * D + off);
        uint4 u5 = *(const uint4*)(g_ef + (size_t)i1.y * D + off);
        uint4 u6 = *(const uint4*)(g_ef + (size_t)i1.z * D + off);
        uint4 u7 = *(const uint4*)(g_ef + (size_t)i1.w * D + off);
        acc_u4(acc, hadd_u4(u0, u1));
        acc_u4(acc, hadd_u4(u2, u3));
        acc_u4(acc, hadd_u4(u4, u5));
        acc_u4(acc, hadd_u4(u6, u7));
    }
    if (i + 4 <= m) {
        int4 i0 = *(const int4*)(sl + i);
        uint4 u0 = *(const uint4*)(g_ef + (size_t)i0.x * D + off);
        uint4 u1 = *(const uint4*)(g_ef + (size_t)i0.y * D + off);
        uint4 u2 = *(const uint4*)(g_ef + (size_t)i0.z * D + off);
        uint4 u3 = *(const uint4*)(g_ef + (size_t)i0.w * D + off);
        acc_u4(acc, hadd_u4(u0, u1));
        acc_u4(acc, hadd_u4(u2, u3));
        i += 4;
    }
    for (; i < m; i++) {
        int e = sl[i];
        acc_u4(acc, *(const uint4*)(g_ef + (size_t)e * D + off));
    }
    float inv = 1.f / (float)max(n, 1);
    float4 o0, o1;
    float x;
    x = acc[0] * inv; o0.x = (x >= 0.f) ? x : 0.01f * x;
    x = acc[1] * inv; o0.y = (x >= 0.f) ? x : 0.01f * x;
    x = acc[2] * inv; o0.z = (x >= 0.f) ? x : 0.01f * x;
    x = acc[3] * inv; o0.w = (x >= 0.f) ? x : 0.01f * x;
    x = acc[4] * inv; o1.x = (x >= 0.f) ? x : 0.01f * x;
    x = acc[5] * inv; o1.y = (x >= 0.f) ? x : 0.01f * x;
    x = acc[6] * inv; o1.z = (x >= 0.f) ? x : 0.01f * x;
    x = acc[7] * inv; o1.w = (x >= 0.f) ? x : 0.01f * x;
    float* op = out + (size_t)v * D + off;
    *(float4*)(op)     = o0;
    *(float4*)(op + 4) = o1;
}

// ---------------- launch -----------------------------------------------------
extern "C" void kernel_launch(void* const* d_in, const int* in_sizes, int n_in,
                              void* d_out, int out_size) {
    const float* X     = (const float*)d_in[0];
    const float* W     = (const float*)d_in[1];
    const float* bias  = (const float*)d_in[2];
    const int*   v_idx = (const int*)d_in[3];
    const int*   e_idx = (const int*)d_in[4];
    float* out = (float*)d_out;

    cudaFuncSetAttribute(k_gemm, cudaFuncAttributeMaxDynamicSharedMemorySize,
                         SMEM_BYTES);

    k_init<<<256, 256>>>(W);
    k_build<<<(NP / 2 + 255) / 256, 256>>>(v_idx, e_idx);

    k_gemm<<<(NV + MT - 1) / MT, 256, SMEM_BYTES>>>(X, bias);

    k_v2e<<<(NE + 7) / 8, 256>>>();
    k_e2v<<<(NV + 7) / 8, 256>>>(out);
}

// round 10
// speedup vs baseline: 1.8893x; 1.1515x over previous
#include <cuda_runtime.h>
#include <cuda_bf16.h>
#include <cuda_fp16.h>
#include <cstdint>

#define NV 50000
#define NE 10000
#define NP 800000
#define D  256
#define CAPE 192
#define CAPV 64

// ---------------- device scratch (no runtime allocation allowed) -----------
__device__ __half g_H[NV * D];                // 25.6 MB projected vertex features (fp16)
__device__ __half g_ef[NE * D];               // 5.1 MB  hyperedge features (fp16)
__device__ int    g_ecnt[NE];
__device__ int    g_vcnt[NV];
__device__ int    g_eslot[NE * CAPE];
__device__ int    g_vslot[NV * CAPV];
__device__ __half g_Wt16[D * D];              // W^T fp16 [n][k]

__device__ __forceinline__ uint32_t smem_u32(const void* p) {
    uint32_t a;
    asm("{ .reg .u64 t; cvta.to.shared.u64 t, %1; cvt.u32.u64 %0, t; }"
        : "=r"(a) : "l"(p));
    return a;
}

// ---------------- init: zero counters + fp16-transpose W --------------------
__global__ void k_init(const float* __restrict__ W) {
    int i = blockIdx.x * blockDim.x + threadIdx.x;   // 65536 threads
    if (i < NE) g_ecnt[i] = 0;
    if (i < NV) g_vcnt[i] = 0;
    int k = i >> 8, n = i & 255;
    g_Wt16[n * D + k] = __float2half_rn(W[k * D + n]);
}

// ---------------- build inverted slot lists (2 pairs / thread) --------------
__global__ void k_build(const int* __restrict__ v_idx,
                        const int* __restrict__ e_idx) {
    int i = blockIdx.x * blockDim.x + threadIdx.x;
    if (i >= NP / 2) return;
    int2 vv = ((const int2*)v_idx)[i];
    int2 ee = ((const int2*)e_idx)[i];
#pragma unroll
    for (int t = 0; t < 2; t++) {
        int v = t ? vv.y : vv.x;
        int e = t ? ee.y : ee.x;
        int pe = atomicAdd(&g_ecnt[e], 1);
        if (pe < CAPE) g_eslot[e * CAPE + pe] = v;
        int pv = atomicAdd(&g_vcnt[v], 1);
        if (pv < CAPV) g_vslot[v * CAPV + pv] = e;
    }
}

// ---------------- fused fp16-split GEMM (HMMA 2-term): H = X*W + b ----------
// CTA tile 128x256, 8 warps (4 M x 2 N), warp tile 32x128.
// All of W^T (fp16, swizzled) resident in SMEM; X double-buffered per 64-chunk.
// H ~= Xh*Wh + Xl*Wh  (dropped: X*Wl ~ 2.8e-4 relative)
#define MT 128
#define KC 64
#define SM_W 0                       // 256 rows x 512 B = 128 KB
#define SM_X (128 * 1024)            // 2 buffers x (XH 16K + XL 16K)
#define SMEM_BYTES (192 * 1024)

extern __shared__ __align__(1024) char dynsm[];

__global__ __launch_bounds__(256, 1) void k_gemm(const float* __restrict__ X,
                                                 const float* __restrict__ bias) {
    char* sm = dynsm;
    const int tid  = threadIdx.x;
    const int wid  = tid >> 5;
    const int lane = tid & 31;
    const int mbase = blockIdx.x * MT;
    const int wm = wid & 3;
    const int wn = wid >> 2;

    const uint32_t sm_u = smem_u32(sm);
    const uint32_t xorv = (uint32_t)(lane & 7) << 4;

    uint32_t aoff[2], boff[8];
#pragma unroll
    for (int t = 0; t < 2; t++)
        aoff[t] = (uint32_t)((wm * 32 + t * 16 + (lane & 15)) * 128 + (lane >> 4) * 16);
#pragma unroll
    for (int jj = 0; jj < 8; jj++)
        boff[jj] = (uint32_t)((wn * 128 + jj * 16 + (lane & 15)) * 512 + (lane >> 4) * 16);

    const int rt  = tid >> 3;      // 0..31
    const int seg = tid & 7;       // 16B segment

    float acc[2][16][4];
#pragma unroll
    for (int t = 0; t < 2; t++)
#pragma unroll
        for (int j = 0; j < 16; j++)
#pragma unroll
            for (int q = 0; q < 4; q++) acc[t][j][q] = 0.f;

    float4 pf[8];

#define LOADX(c) do {                                                          \
    int kc = (c) * KC;                                                         \
    _Pragma("unroll")                                                          \
    for (int q = 0; q < 4; q++) {                                              \
        int gr = mbase + 32 * q + rt;                                          \
        if (gr < NV) {                                                         \
            const float* p = X + (size_t)gr * D + kc + seg * 8;                \
            pf[2 * q]     = *(const float4*)(p);                               \
            pf[2 * q + 1] = *(const float4*)(p + 4);                           \
        } else {                                                               \
            pf[2 * q] = pf[2 * q + 1] = make_float4(0.f, 0.f, 0.f, 0.f);       \
        }                                                                      \
    } } while (0)

// convert pf regs -> fp16 hi/lo tiles in buffer b
#define CONVX(b) do {                                                          \
    _Pragma("unroll")                                                          \
    for (int q = 0; q < 4; q++) {                                              \
        int r = 32 * q + rt;                                                   \
        uint32_t off = (uint32_t)(r * 128 + seg * 16);                         \
        uint32_t sw  = off ^ (uint32_t)((r & 7) << 4);                         \
        float f[8];                                                            \
        f[0]=pf[2*q].x; f[1]=pf[2*q].y; f[2]=pf[2*q].z; f[3]=pf[2*q].w;        \
        f[4]=pf[2*q+1].x; f[5]=pf[2*q+1].y; f[6]=pf[2*q+1].z; f[7]=pf[2*q+1].w;\
        uint32_t hw[4], lw[4];                                                 \
        _Pragma("unroll")                                                      \
        for (int p2 = 0; p2 < 4; p2++) {                                       \
            __half h0 = __float2half_rn(f[2*p2]);                              \
            __half h1 = __float2half_rn(f[2*p2+1]);                            \
            __half l0 = __float2half_rn(f[2*p2]   - __half2float(h0));         \
            __half l1 = __float2half_rn(f[2*p2+1] - __half2float(h1));         \
            hw[p2] = ((uint32_t)__half_as_ushort(h1) << 16) | __half_as_ushort(h0); \
            lw[p2] = ((uint32_t)__half_as_ushort(l1) << 16) | __half_as_ushort(l0); \
        }                                                                      \
        char* xb = sm + SM_X + (b) * 32768;                                    \
        *(uint4*)(xb + sw)         = make_uint4(hw[0], hw[1], hw[2], hw[3]);   \
        *(uint4*)(xb + 16384 + sw) = make_uint4(lw[0], lw[1], lw[2], lw[3]);   \
    } } while (0)

    LOADX(0);

    // stage ALL of W^T into SMEM once (swizzled per 128B block)
#pragma unroll
    for (int q = 0; q < 8; q++) {
        int n = 32 * q + rt;
        const __half* wp = g_Wt16 + (size_t)n * D;
        uint32_t rowb = (uint32_t)(n * 512);
        uint32_t sx   = (uint32_t)((n & 7) << 4);
#pragma unroll
        for (int c = 0; c < 4; c++) {
            uint4 v = *(const uint4*)(wp + c * 64 + seg * 8);
            uint32_t inner = (uint32_t)(c * 128 + seg * 16) ^ sx;
            *(uint4*)(sm + SM_W + rowb + (inner & 127) + (inner & ~127u)) = v;
        }
    }
    CONVX(0);
    __syncthreads();

    for (int c = 0; c < 4; c++) {
        if (c < 3) LOADX(c + 1);
        const uint32_t xbase = sm_u + SM_X + (uint32_t)((c & 1) * 32768);
        const uint32_t koff  = (uint32_t)(c * 128);
#pragma unroll
        for (int s = 0; s < 4; s++) {
            const uint32_t kb = (uint32_t)(s * 32);
            uint32_t arh[2][4], arl[2][4], brh[8][4];
#pragma unroll
            for (int t = 0; t < 2; t++) {
                uint32_t ah = xbase + ((aoff[t] + kb) ^ xorv);
                asm volatile(
                    "ldmatrix.sync.aligned.m8n8.x4.shared.b16 {%0,%1,%2,%3}, [%4];"
                    : "=r"(arh[t][0]), "=r"(arh[t][1]), "=r"(arh[t][2]), "=r"(arh[t][3])
                    : "r"(ah));
                uint32_t al = xbase + 16384 + ((aoff[t] + kb) ^ xorv);
                asm volatile(
                    "ldmatrix.sync.aligned.m8n8.x4.shared.b16 {%0,%1,%2,%3}, [%4];"
                    : "=r"(arl[t][0]), "=r"(arl[t][1]), "=r"(arl[t][2]), "=r"(arl[t][3])
                    : "r"(al));
            }
#pragma unroll
            for (int jj = 0; jj < 8; jj++) {
                uint32_t bh = sm_u + SM_W + ((boff[jj] + koff + kb) ^ xorv);
                asm volatile(
                    "ldmatrix.sync.aligned.m8n8.x4.shared.b16 {%0,%1,%2,%3}, [%4];"
                    : "=r"(brh[jj][0]), "=r"(brh[jj][1]), "=r"(brh[jj][2]), "=r"(brh[jj][3])
                    : "r"(bh));
            }
#pragma unroll
            for (int t = 0; t < 2; t++)
#pragma unroll
                for (int j = 0; j < 16; j++) {
                    const int u = j >> 1, h = j & 1;
                    asm volatile(
                        "mma.sync.aligned.m16n8k16.row.col.f32.f16.f16.f32 "
                        "{%0,%1,%2,%3}, {%4,%5,%6,%7}, {%8,%9}, {%0,%1,%2,%3};"
                        : "+f"(acc[t][j][0]), "+f"(acc[t][j][1]),
                          "+f"(acc[t][j][2]), "+f"(acc[t][j][3])
                        : "r"(arh[t][0]), "r"(arh[t][1]), "r"(arh[t][2]), "r"(arh[t][3]),
                          "r"(brh[u][h]), "r"(brh[u][2 + h]));
                    asm volatile(
                        "mma.sync.aligned.m16n8k16.row.col.f32.f16.f16.f32 "
                        "{%0,%1,%2,%3}, {%4,%5,%6,%7}, {%8,%9}, {%0,%1,%2,%3};"
                        : "+f"(acc[t][j][0]), "+f"(acc[t][j][1]),
                          "+f"(acc[t][j][2]), "+f"(acc[t][j][3])
                        : "r"(arl[t][0]), "r"(arl[t][1]), "r"(arl[t][2]), "r"(arl[t][3]),
                          "r"(brh[u][h]), "r"(brh[u][2 + h]));
                }
        }
        if (c < 3) {
            CONVX((c + 1) & 1);
            __syncthreads();
        }
    }

    // epilogue: C frags + bias -> g_H (fp16)
    const int r0 = lane >> 2;
    const int c2 = (lane & 3) * 2;
#pragma unroll
    for (int t = 0; t < 2; t++) {
        int row = mbase + wm * 32 + t * 16 + r0;
#pragma unroll
        for (int j = 0; j < 16; j++) {
            int col = wn * 128 + j * 8 + c2;
            float2 bv = *(const float2*)(bias + col);
            if (row < NV) {
                __half2 o = __floats2half2_rn(acc[t][j][0] + bv.x,
                                              acc[t][j][1] + bv.y);
                *(__half2*)(g_H + (size_t)row * D + col) = o;
            }
            if (row + 8 < NV) {
                __half2 o = __floats2half2_rn(acc[t][j][2] + bv.x,
                                              acc[t][j][3] + bv.y);
                *(__half2*)(g_H + (size_t)(row + 8) * D + col) = o;
            }
        }
    }
#undef LOADX
#undef CONVX
}

// ---- helper: accumulate a half2-packed uint4 into 8 fp32 lanes --------------
__device__ __forceinline__ void acc_u4(float* acc, uint4 u) {
    float2 a = __half22float2(*(__half2*)&u.x);
    float2 b = __half22float2(*(__half2*)&u.y);
    float2 c = __half22float2(*(__half2*)&u.z);
    float2 d = __half22float2(*(__half2*)&u.w);
    acc[0] += a.x; acc[1] += a.y; acc[2] += b.x; acc[3] += b.y;
    acc[4] += c.x; acc[5] += c.y; acc[6] += d.x; acc[7] += d.y;
}
__device__ __forceinline__ uint4 hadd_u4(uint4 p, uint4 q) {
    uint4 r;
    *(__half2*)&r.x = __hadd2(*(__half2*)&p.x, *(__half2*)&q.x);
    *(__half2*)&r.y = __hadd2(*(__half2*)&p.y, *(__half2*)&q.y);
    *(__half2*)&r.z = __hadd2(*(__half2*)&p.z, *(__half2*)&q.z);
    *(__half2*)&r.w = __hadd2(*(__half2*)&p.w, *(__half2*)&q.w);
    return r;
}

// ---------------- v2e mean: fp16 gather, pairwise fp16 + fp32 accum ----------
__global__ __launch_bounds__(256) void k_v2e() {
    const int g    = threadIdx.x >> 5;
    const int lane = threadIdx.x & 31;
    const int e    = blockIdx.x * 8 + g;
    if (e >= NE) return;

    const int n = g_ecnt[e];
    const int m = min(n, CAPE);
    const int* __restrict__ sl = g_eslot + e * CAPE;
    const int off = lane * 8;

    float acc[8];
#pragma unroll
    for (int q = 0; q < 8; q++) acc[q] = 0.f;

    int i = 0;
    for (; i + 8 <= m; i += 8) {
        int4 i0 = *(const int4*)(sl + i);
        int4 i1 = *(const int4*)(sl + i + 4);
        uint4 u0 = *(const uint4*)(g_H + (size_t)i0.x * D + off);
        uint4 u1 = *(const uint4*)(g_H + (size_t)i0.y * D + off);
        uint4 u2 = *(const uint4*)(g_H + (size_t)i0.z * D + off);
        uint4 u3 = *(const uint4*)(g_H + (size_t)i0.w * D + off);
        uint4 u4 = *(const uint4*)(g_H + (size_t)i1.x * D + off);
        uint4 u5 = *(const uint4*)(g_H + (size_t)i1.y * D + off);
        uint4 u6 = *(const uint4*)(g_H + (size_t)i1.z * D + off);
        uint4 u7 = *(const uint4*)(g_H + (size_t)i1.w * D + off);
        acc_u4(acc, hadd_u4(u0, u1));
        acc_u4(acc, hadd_u4(u2, u3));
        acc_u4(acc, hadd_u4(u4, u5));
        acc_u4(acc, hadd_u4(u6, u7));
    }
    for (; i < m; i++) {
        int v = sl[i];
        acc_u4(acc, *(const uint4*)(g_H + (size_t)v * D + off));
    }
    float inv = 1.f / (float)max(n, 1);
    uint4 o;
    ((__half2*)&o.x)[0] = __floats2half2_rn(acc[0] * inv, acc[1] * inv);
    ((__half2*)&o.y)[0] = __floats2half2_rn(acc[2] * inv, acc[3] * inv);
    ((__half2*)&o.z)[0] = __floats2half2_rn(acc[4] * inv, acc[5] * inv);
    ((__half2*)&o.w)[0] = __floats2half2_rn(acc[6] * inv, acc[7] * inv);
    *(uint4*)(g_ef + (size_t)e * D + off) = o;
}

// ---------------- e2v mean + leaky relu, fp32 out ----------------------------
__global__ __launch_bounds__(256) void k_e2v(float* __restrict__ out) {
    const int g    = threadIdx.x >> 5;
    const int lane = threadIdx.x & 31;
    const int v    = blockIdx.x * 8 + g;
    if (v >= NV) return;

    const int n = g_vcnt[v];
    const int m = min(n, CAPV);
    const int* __restrict__ sl = g_vslot + v * CAPV;
    const int off = lane * 8;

    float acc[8];
#pragma unroll
    for (int q = 0; q < 8; q++) acc[q] = 0.f;

    int i = 0;
    for (; i + 8 <= m; i += 8) {
        int4 i0 = *(const int4*)(sl + i);
        int4 i1 = *(const int4*)(sl + i + 4);
        uint4 u0 = *(const uint4*)(g_ef + (size_t)i0.x * D + off);
        uint4 u1 = *(const uint4*)(g_ef + (size_t)i0.y * D + off);
        uint4 u2 = *(const uint4*)(g_ef + (size_t)i0.z * D + off);
        uint4 u3 = *(const uint4*)(g_ef + (size_t)i0.w * D + off);
        uint4 u4 = *(const uint4*)(g_ef + (size_t)i1.x * D + off);
        uint4 u5 = *(const uint4*)(g_ef + (size_t)i1.y * D + off);
        uint4 u6 = *(const uint4*)(g_ef + (size_t)i1.z * D + off);
        uint4 u7 = *(const uint4*)(g_ef + (size_t)i1.w * D + off);
        acc_u4(acc, hadd_u4(u0, u1));
        acc_u4(acc, hadd_u4(u2, u3));
        acc_u4(acc, hadd_u4(u4, u5));
        acc_u4(acc, hadd_u4(u6, u7));
    }
    if (i + 4 <= m) {
        int4 i0 = *(const int4*)(sl + i);
        uint4 u0 = *(const uint4*)(g_ef + (size_t)i0.x * D + off);
        uint4 u1 = *(const uint4*)(g_ef + (size_t)i0.y * D + off);
        uint4 u2 = *(const uint4*)(g_ef + (size_t)i0.z * D + off);
        uint4 u3 = *(const uint4*)(g_ef + (size_t)i0.w * D + off);
        acc_u4(acc, hadd_u4(u0, u1));
        acc_u4(acc, hadd_u4(u2, u3));
        i += 4;
    }
    for (; i < m; i++) {
        int e = sl[i];
        acc_u4(acc, *(const uint4*)(g_ef + (size_t)e * D + off));
    }
    float inv = 1.f / (float)max(n, 1);
    float4 o0, o1;
    float x;
    x = acc[0] * inv; o0.x = (x >= 0.f) ? x : 0.01f * x;
    x = acc[1] * inv; o0.y = (x >= 0.f) ? x : 0.01f * x;
    x = acc[2] * inv; o0.z = (x >= 0.f) ? x : 0.01f * x;
    x = acc[3] * inv; o0.w = (x >= 0.f) ? x : 0.01f * x;
    x = acc[4] * inv; o1.x = (x >= 0.f) ? x : 0.01f * x;
    x = acc[5] * inv; o1.y = (x >= 0.f) ? x : 0.01f * x;
    x = acc[6] * inv; o1.z = (x >= 0.f) ? x : 0.01f * x;
    x = acc[7] * inv; o1.w = (x >= 0.f) ? x : 0.01f * x;
    float* op = out + (size_t)v * D + off;
    *(float4*)(op)     = o0;
    *(float4*)(op + 4) = o1;
}

// ---------------- launch -----------------------------------------------------
extern "C" void kernel_launch(void* const* d_in, const int* in_sizes, int n_in,
                              void* d_out, int out_size) {
    const float* X     = (const float*)d_in[0];
    const float* W     = (const float*)d_in[1];
    const float* bias  = (const float*)d_in[2];
    const int*   v_idx = (const int*)d_in[3];
    const int*   e_idx = (const int*)d_in[4];
    float* out = (float*)d_out;

    cudaFuncSetAttribute(k_gemm, cudaFuncAttributeMaxDynamicSharedMemorySize,
                         SMEM_BYTES);

    k_init<<<256, 256>>>(W);
    k_build<<<(NP / 2 + 255) / 256, 256>>>(v_idx, e_idx);

    k_gemm<<<(NV + MT - 1) / MT, 256, SMEM_BYTES>>>(X, bias);

    k_v2e<<<(NE + 7) / 8, 256>>>();
    k_e2v<<<(NV + 7) / 8, 256>>>(out);
}

// round 13
// speedup vs baseline: 2.2743x; 1.2038x over previous
#include <cuda_runtime.h>
#include <cuda_bf16.h>
#include <cuda_fp16.h>
#include <cstdint>

#define NV 50000
#define NE 10000
#define NP 800000
#define D  256
#define CAPE 192
#define CAPV 64

// ---------------- device scratch (no runtime allocation allowed) -----------
__device__ __half g_H[NV * D];                // 25.6 MB projected vertex features (fp16)
__device__ __half g_ef[NE * D];               // 5.1 MB  hyperedge features (fp16)
__device__ int    g_ecnt[NE];
__device__ int    g_vcnt[NV];
__device__ int    g_eslot[NE * CAPE];
__device__ int    g_vslot[NV * CAPV];
__device__ __half g_Wt16[D * D];              // W^T fp16 [n][k]

__device__ __forceinline__ uint32_t smem_u32(const void* p) {
    uint32_t a;
    asm("{ .reg .u64 t; cvta.to.shared.u64 t, %1; cvt.u32.u64 %0, t; }"
        : "=r"(a) : "l"(p));
    return a;
}

// ---------------- init: zero counters + fp16-transpose W --------------------
__global__ void k_init(const float* __restrict__ W) {
    int i = blockIdx.x * blockDim.x + threadIdx.x;   // 65536 threads
    if (i < NE) g_ecnt[i] = 0;
    if (i < NV) g_vcnt[i] = 0;
    int k = i >> 8, n = i & 255;
    g_Wt16[n * D + k] = __float2half_rn(W[k * D + n]);
}

// ---------------- build inverted slot lists (2 pairs / thread) --------------
__global__ void k_build(const int* __restrict__ v_idx,
                        const int* __restrict__ e_idx) {
    int i = blockIdx.x * blockDim.x + threadIdx.x;
    if (i >= NP / 2) return;
    int2 vv = ((const int2*)v_idx)[i];
    int2 ee = ((const int2*)e_idx)[i];
#pragma unroll
    for (int t = 0; t < 2; t++) {
        int v = t ? vv.y : vv.x;
        int e = t ? ee.y : ee.x;
        int pe = atomicAdd(&g_ecnt[e], 1);
        if (pe < CAPE) g_eslot[e * CAPE + pe] = v;
        int pv = atomicAdd(&g_vcnt[v], 1);
        if (pv < CAPV) g_vslot[v * CAPV + pv] = e;
    }
}

// ---------------- fp16 GEMM (HMMA single-term): H = X*W + b -----------------
// CTA tile 128x256, 8 warps (4 M x 2 N), warp tile 32x128.
// All of W^T (fp16, swizzled) resident in SMEM; X (fp16 hi) double-buffered.
// H ~= Xh*Wh  (dropped: X*Wl ~2.8e-4, Xl*W ~2.8e-4 relative)
#define MT 128
#define KC 64
#define SM_W 0                       // 256 rows x 512 B = 128 KB
#define SM_X (128 * 1024)            // 2 buffers x 16 KB
#define SMEM_BYTES (160 * 1024)

extern __shared__ __align__(1024) char dynsm[];

__global__ __launch_bounds__(256, 1) void k_gemm(const float* __restrict__ X,
                                                 const float* __restrict__ bias) {
    char* sm = dynsm;
    const int tid  = threadIdx.x;
    const int wid  = tid >> 5;
    const int lane = tid & 31;
    const int mbase = blockIdx.x * MT;
    const int wm = wid & 3;
    const int wn = wid >> 2;

    const uint32_t sm_u = smem_u32(sm);
    const uint32_t xorv = (uint32_t)(lane & 7) << 4;

    uint32_t aoff[2], boff[8];
#pragma unroll
    for (int t = 0; t < 2; t++)
        aoff[t] = (uint32_t)((wm * 32 + t * 16 + (lane & 15)) * 128 + (lane >> 4) * 16);
#pragma unroll
    for (int jj = 0; jj < 8; jj++)
        boff[jj] = (uint32_t)((wn * 128 + jj * 16 + (lane & 15)) * 512 + (lane >> 4) * 16);

    const int rt  = tid >> 3;      // 0..31
    const int seg = tid & 7;       // 16B segment

    float acc[2][16][4];
#pragma unroll
    for (int t = 0; t < 2; t++)
#pragma unroll
        for (int j = 0; j < 16; j++)
#pragma unroll
            for (int q = 0; q < 4; q++) acc[t][j][q] = 0.f;

    float4 pf[8];

#define LOADX(c) do {                                                          \
    int kc = (c) * KC;                                                         \
    _Pragma("unroll")                                                          \
    for (int q = 0; q < 4; q++) {                                              \
        int gr = mbase + 32 * q + rt;                                          \
        if (gr < NV) {                                                         \
            const float* p = X + (size_t)gr * D + kc + seg * 8;                \
            pf[2 * q]     = *(const float4*)(p);                               \
            pf[2 * q + 1] = *(const float4*)(p + 4);                           \
        } else {                                                               \
            pf[2 * q] = pf[2 * q + 1] = make_float4(0.f, 0.f, 0.f, 0.f);       \
        }                                                                      \
    } } while (0)

// convert pf regs -> fp16 tile in buffer b
#define CONVX(b) do {                                                          \
    _Pragma("unroll")                                                          \
    for (int q = 0; q < 4; q++) {                                              \
        int r = 32 * q + rt;                                                   \
        uint32_t off = (uint32_t)(r * 128 + seg * 16);                         \
        uint32_t sw  = off ^ (uint32_t)((r & 7) << 4);                         \
        __half2 h0 = __floats2half2_rn(pf[2*q].x,   pf[2*q].y);                \
        __half2 h1 = __floats2half2_rn(pf[2*q].z,   pf[2*q].w);                \
        __half2 h2 = __floats2half2_rn(pf[2*q+1].x, pf[2*q+1].y);              \
        __half2 h3 = __floats2half2_rn(pf[2*q+1].z, pf[2*q+1].w);              \
        char* xb = sm + SM_X + (b) * 16384;                                    \
        *(uint4*)(xb + sw) = make_uint4(*(uint32_t*)&h0, *(uint32_t*)&h1,      \
                                        *(uint32_t*)&h2, *(uint32_t*)&h3);     \
    } } while (0)

    LOADX(0);

    // stage ALL of W^T into SMEM once (swizzled per 128B block)
#pragma unroll
    for (int q = 0; q < 8; q++) {
        int n = 32 * q + rt;
        const __half* wp = g_Wt16 + (size_t)n * D;
        uint32_t rowb = (uint32_t)(n * 512);
        uint32_t sx   = (uint32_t)((n & 7) << 4);
#pragma unroll
        for (int c = 0; c < 4; c++) {
            uint4 v = *(const uint4*)(wp + c * 64 + seg * 8);
            uint32_t inner = (uint32_t)(c * 128 + seg * 16) ^ sx;
            *(uint4*)(sm + SM_W + rowb + (inner & 127) + (inner & ~127u)) = v;
        }
    }
    CONVX(0);
    __syncthreads();

    for (int c = 0; c < 4; c++) {
        if (c < 3) LOADX(c + 1);
        const uint32_t xbase = sm_u + SM_X + (uint32_t)((c & 1) * 16384);
        const uint32_t koff  = (uint32_t)(c * 128);
#pragma unroll
        for (int s = 0; s < 4; s++) {
            const uint32_t kb = (uint32_t)(s * 32);
            uint32_t ar[2][4], br[8][4];
#pragma unroll
            for (int t = 0; t < 2; t++) {
                uint32_t ah = xbase + ((aoff[t] + kb) ^ xorv);
                asm volatile(
                    "ldmatrix.sync.aligned.m8n8.x4.shared.b16 {%0,%1,%2,%3}, [%4];"
                    : "=r"(ar[t][0]), "=r"(ar[t][1]), "=r"(ar[t][2]), "=r"(ar[t][3])
                    : "r"(ah));
            }
#pragma unroll
            for (int jj = 0; jj < 8; jj++) {
                uint32_t bh = sm_u + SM_W + ((boff[jj] + koff + kb) ^ xorv);
                asm volatile(
                    "ldmatrix.sync.aligned.m8n8.x4.shared.b16 {%0,%1,%2,%3}, [%4];"
                    : "=r"(br[jj][0]), "=r"(br[jj][1]), "=r"(br[jj][2]), "=r"(br[jj][3])
                    : "r"(bh));
            }
#pragma unroll
            for (int t = 0; t < 2; t++)
#pragma unroll
                for (int j = 0; j < 16; j++) {
                    const int u = j >> 1, h = j & 1;
                    asm volatile(
                        "mma.sync.aligned.m16n8k16.row.col.f32.f16.f16.f32 "
                        "{%0,%1,%2,%3}, {%4,%5,%6,%7}, {%8,%9}, {%0,%1,%2,%3};"
                        : "+f"(acc[t][j][0]), "+f"(acc[t][j][1]),
                          "+f"(acc[t][j][2]), "+f"(acc[t][j][3])
                        : "r"(ar[t][0]), "r"(ar[t][1]), "r"(ar[t][2]), "r"(ar[t][3]),
                          "r"(br[u][h]), "r"(br[u][2 + h]));
                }
        }
        if (c < 3) {
            CONVX((c + 1) & 1);
            __syncthreads();
        }
    }

    // epilogue: C frags + bias -> g_H (fp16)
    const int r0 = lane >> 2;
    const int c2 = (lane & 3) * 2;
#pragma unroll
    for (int t = 0; t < 2; t++) {
        int row = mbase + wm * 32 + t * 16 + r0;
#pragma unroll
        for (int j = 0; j < 16; j++) {
            int col = wn * 128 + j * 8 + c2;
            float2 bv = *(const float2*)(bias + col);
            if (row < NV) {
                __half2 o = __floats2half2_rn(acc[t][j][0] + bv.x,
                                              acc[t][j][1] + bv.y);
                *(__half2*)(g_H + (size_t)row * D + col) = o;
            }
            if (row + 8 < NV) {
                __half2 o = __floats2half2_rn(acc[t][j][2] + bv.x,
                                              acc[t][j][3] + bv.y);
                *(__half2*)(g_H + (size_t)(row + 8) * D + col) = o;
            }
        }
    }
#undef LOADX
#undef CONVX
}

// ---- helper: accumulate a half2-packed uint4 into 8 fp32 lanes --------------
__device__ __forceinline__ void acc_u4(float* acc, uint4 u) {
    float2 a = __half22float2(*(__half2*)&u.x);
    float2 b = __half22float2(*(__half2*)&u.y);
    float2 c = __half22float2(*(__half2*)&u.z);
    float2 d = __half22float2(*(__half2*)&u.w);
    acc[0] += a.x; acc[1] += a.y; acc[2] += b.x; acc[3] += b.y;
    acc[4] += c.x; acc[5] += c.y; acc[6] += d.x; acc[7] += d.y;
}
__device__ __forceinline__ uint4 hadd_u4(uint4 p, uint4 q) {
    uint4 r;
    *(__half2*)&r.x = __hadd2(*(__half2*)&p.x, *(__half2*)&q.x);
    *(__half2*)&r.y = __hadd2(*(__half2*)&p.y, *(__half2*)&q.y);
    *(__half2*)&r.z = __hadd2(*(__half2*)&p.z, *(__half2*)&q.z);
    *(__half2*)&r.w = __hadd2(*(__half2*)&p.w, *(__half2*)&q.w);
    return r;
}

// ---------------- v2e mean: fp16 gather, pairwise fp16 + fp32 accum ----------
__global__ __launch_bounds__(256) void k_v2e() {
    const int g    = threadIdx.x >> 5;
    const int lane = threadIdx.x & 31;
    const int e    = blockIdx.x * 8 + g;
    if (e >= NE) return;

    const int n = g_ecnt[e];
    const int m = min(n, CAPE);
    const int* __restrict__ sl = g_eslot + e * CAPE;
    const int off = lane * 8;

    float acc[8];
#pragma unroll
    for (int q = 0; q < 8; q++) acc[q] = 0.f;

    int i = 0;
    for (; i + 8 <= m; i += 8) {
        int4 i0 = *(const int4*)(sl + i);
        int4 i1 = *(const int4*)(sl + i + 4);
        uint4 u0 = *(const uint4*)(g_H + (size_t)i0.x * D + off);
        uint4 u1 = *(const uint4*)(g_H + (size_t)i0.y * D + off);
        uint4 u2 = *(const uint4*)(g_H + (size_t)i0.z * D + off);
        uint4 u3 = *(const uint4*)(g_H + (size_t)i0.w * D + off);
        uint4 u4 = *(const uint4*)(g_H + (size_t)i1.x * D + off);
        uint4 u5 = *(const uint4*)(g_H + (size_t)i1.y * D + off);
        uint4 u6 = *(const uint4*)(g_H + (size_t)i1.z * D + off);
        uint4 u7 = *(const uint4*)(g_H + (size_t)i1.w * D + off);
        acc_u4(acc, hadd_u4(u0, u1));
        acc_u4(acc, hadd_u4(u2, u3));
        acc_u4(acc, hadd_u4(u4, u5));
        acc_u4(acc, hadd_u4(u6, u7));
    }
    for (; i < m; i++) {
        int v = sl[i];
        acc_u4(acc, *(const uint4*)(g_H + (size_t)v * D + off));
    }
    float inv = 1.f / (float)max(n, 1);
    uint4 o;
    ((__half2*)&o.x)[0] = __floats2half2_rn(acc[0] * inv, acc[1] * inv);
    ((__half2*)&o.y)[0] = __floats2half2_rn(acc[2] * inv, acc[3] * inv);
    ((__half2*)&o.z)[0] = __floats2half2_rn(acc[4] * inv, acc[5] * inv);
    ((__half2*)&o.w)[0] = __floats2half2_rn(acc[6] * inv, acc[7] * inv);
    *(uint4*)(g_ef + (size_t)e * D + off) = o;
}

// ---------------- e2v mean + leaky relu, fp32 out ----------------------------
__global__ __launch_bounds__(256) void k_e2v(float* __restrict__ out) {
    const int g    = threadIdx.x >> 5;
    const int lane = threadIdx.x & 31;
    const int v    = blockIdx.x * 8 + g;
    if (v >= NV) return;

    const int n = g_vcnt[v];
    const int m = min(n, CAPV);
    const int* __restrict__ sl = g_vslot + v * CAPV;
    const int off = lane * 8;

    float acc[8];
#pragma unroll
    for (int q = 0; q < 8; q++) acc[q] = 0.f;

    int i = 0;
    for (; i + 8 <= m; i += 8) {
        int4 i0 = *(const int4*)(sl + i);
        int4 i1 = *(const int4*)(sl + i + 4);
        uint4 u0 = *(const uint4*)(g_ef + (size_t)i0.x * D + off);
        uint4 u1 = *(const uint4*)(g_ef + (size_t)i0.y * D + off);
        uint4 u2 = *(const uint4*)(g_ef + (size_t)i0.z * D + off);
        uint4 u3 = *(const uint4*)(g_ef + (size_t)i0.w * D + off);
        uint4 u4 = *(const uint4*)(g_ef + (size_t)i1.x * D + off);
        uint4 u5 = *(const uint4*)(g_ef + (size_t)i1.y * D + off);
        uint4 u6 = *(const uint4*)(g_ef + (size_t)i1.z * D + off);
        uint4 u7 = *(const uint4*)(g_ef + (size_t)i1.w * D + off);
        acc_u4(acc, hadd_u4(u0, u1));
        acc_u4(acc, hadd_u4(u2, u3));
        acc_u4(acc, hadd_u4(u4, u5));
        acc_u4(acc, hadd_u4(u6, u7));
    }
    if (i + 4 <= m) {
        int4 i0 = *(const int4*)(sl + i);
        uint4 u0 = *(const uint4*)(g_ef + (size_t)i0.x * D + off);
        uint4 u1 = *(const uint4*)(g_ef + (size_t)i0.y * D + off);
        uint4 u2 = *(const uint4*)(g_ef + (size_t)i0.z * D + off);
        uint4 u3 = *(const uint4*)(g_ef + (size_t)i0.w * D + off);
        acc_u4(acc, hadd_u4(u0, u1));
        acc_u4(acc, hadd_u4(u2, u3));
        i += 4;
    }
    for (; i < m; i++) {
        int e = sl[i];
        acc_u4(acc, *(const uint4*)(g_ef + (size_t)e * D + off));
    }
    float inv = 1.f / (float)max(n, 1);
    float4 o0, o1;
    float x;
    x = acc[0] * inv; o0.x = (x >= 0.f) ? x : 0.01f * x;
    x = acc[1] * inv; o0.y = (x >= 0.f) ? x : 0.01f * x;
    x = acc[2] * inv; o0.z = (x >= 0.f) ? x : 0.01f * x;
    x = acc[3] * inv; o0.w = (x >= 0.f) ? x : 0.01f * x;
    x = acc[4] * inv; o1.x = (x >= 0.f) ? x : 0.01f * x;
    x = acc[5] * inv; o1.y = (x >= 0.f) ? x : 0.01f * x;
    x = acc[6] * inv; o1.z = (x >= 0.f) ? x : 0.01f * x;
    x = acc[7] * inv; o1.w = (x >= 0.f) ? x : 0.01f * x;
    float* op = out + (size_t)v * D + off;
    *(float4*)(op)     = o0;
    *(float4*)(op + 4) = o1;
}

// ---------------- launch -----------------------------------------------------
extern "C" void kernel_launch(void* const* d_in, const int* in_sizes, int n_in,
                              void* d_out, int out_size) {
    const float* X     = (const float*)d_in[0];
    const float* W     = (const float*)d_in[1];
    const float* bias  = (const float*)d_in[2];
    const int*   v_idx = (const int*)d_in[3];
    const int*   e_idx = (const int*)d_in[4];
    float* out = (float*)d_out;

    cudaFuncSetAttribute(k_gemm, cudaFuncAttributeMaxDynamicSharedMemorySize,
                         SMEM_BYTES);

    k_init<<<256, 256>>>(W);
    k_build<<<(NP / 2 + 255) / 256, 256>>>(v_idx, e_idx);

    k_gemm<<<(NV + MT - 1) / MT, 256, SMEM_BYTES>>>(X, bias);

    k_v2e<<<(NE + 7) / 8, 256>>>();
    k_e2v<<<(NV + 7) / 8, 256>>>(out);
}